// round 1
// baseline (speedup 1.0000x reference)
#include <cuda_runtime.h>
#include <cuda_bf16.h>
#include <cstdint>

// ---------------- problem constants ----------------
#define BATCH 2
#define S_LEN 2048
#define PREV_LEN 1024
#define T_LEN 3072            // PREV + S (cache_limit=4096 > 3072, no trim)
#define DIM 2048
#define HEADS 16
#define HD 128
#define FF_DIM 8192
#define ROWS (BATCH * S_LEN)  // 4096
#define QK_SCALE 0.08838834764831845f  // 1/sqrt(128)

// out layout: x (2,2048,2048) | k_attn (2,16,3072,128) | v_attn (2,16,3072,128)
#define OUT_X_ELEMS  (BATCH * S_LEN * DIM)          // 8388608
#define OUT_KV_ELEMS (BATCH * HEADS * T_LEN * HD)   // 12582912

// ---------------- scratch (device globals; no allocation allowed) --------
__device__ float g_h  [ROWS * DIM];
__device__ float g_qt [ROWS * DIM];
__device__ float g_kt [ROWS * DIM];
__device__ float g_vt [ROWS * DIM];
__device__ float g_q  [ROWS * DIM];   // (b,h,s,d)
__device__ float g_o  [ROWS * DIM];   // (b,s,dim)
__device__ float g_x1 [ROWS * DIM];
__device__ float g_h2 [ROWS * DIM];
__device__ float g_g  [ROWS * FF_DIM];

// ---------------- rmsnorm ----------------
__global__ __launch_bounds__(256) void rmsnorm_kernel(
    const float* __restrict__ x, const float* __restrict__ w, float* __restrict__ out)
{
    __shared__ float red[256];
    const int tid = threadIdx.x;
    const float* xp = x + (size_t)blockIdx.x * DIM + tid * 8;
    float4 a = *(const float4*)xp;
    float4 b = *(const float4*)(xp + 4);
    float s = a.x*a.x + a.y*a.y + a.z*a.z + a.w*a.w
            + b.x*b.x + b.y*b.y + b.z*b.z + b.w*b.w;
    red[tid] = s;
    __syncthreads();
    #pragma unroll
    for (int off = 128; off > 0; off >>= 1) {
        if (tid < off) red[tid] += red[tid + off];
        __syncthreads();
    }
    float scale = rsqrtf(red[0] * (1.0f / DIM) + 1e-6f);
    const float* wp = w + tid * 8;
    float4 wa = *(const float4*)wp;
    float4 wb = *(const float4*)(wp + 4);
    float* op = out + (size_t)blockIdx.x * DIM + tid * 8;
    *(float4*)op       = make_float4(a.x*scale*wa.x, a.y*scale*wa.y, a.z*scale*wa.z, a.w*scale*wa.w);
    *(float4*)(op + 4) = make_float4(b.x*scale*wb.x, b.y*scale*wb.y, b.z*scale*wb.z, b.w*scale*wb.w);
}

// ---------------- generic fp32 GEMM, 128x128x16 tile, 8x8/thread ----------
// MODE 0: C = A@B + bias
// MODE 1: C = A@B + bias + extra (residual, MxN)
// MODE 2: C = silu(extra) * (A@B + bias)    (extra may alias C)
template<int MODE>
__global__ __launch_bounds__(256) void gemm_kernel(
    const float* __restrict__ A, const float* __restrict__ B,
    const float* __restrict__ bias, const float* __restrict__ extra,
    float* __restrict__ C, int M, int N, int K)
{
    __shared__ float As[16][128];
    __shared__ float Bs[16][132];
    const int tid = threadIdx.x;
    const size_t row0 = (size_t)blockIdx.y * 128;
    const size_t col0 = (size_t)blockIdx.x * 128;
    const int ty = tid >> 4, tx = tid & 15;

    float acc[8][8];
    #pragma unroll
    for (int i = 0; i < 8; i++)
        #pragma unroll
        for (int j = 0; j < 8; j++) acc[i][j] = 0.f;

    const int a_r = tid >> 2;          // 0..63
    const int a_c = (tid & 3) * 4;     // 0..12
    const int b_r = tid >> 5;          // 0..7
    const int b_c = (tid & 31) * 4;    // 0..124

    const float* Aptr = A + (row0 + a_r) * (size_t)K + a_c;
    const float* Bptr = B + (size_t)b_r * N + col0 + b_c;

    for (int k0 = 0; k0 < K; k0 += 16) {
        float4 a0 = *(const float4*)(Aptr + k0);
        float4 a1 = *(const float4*)(Aptr + (size_t)64 * K + k0);
        float4 b0 = *(const float4*)(Bptr + (size_t)k0 * N);
        float4 b1 = *(const float4*)(Bptr + (size_t)(k0 + 8) * N);
        As[a_c + 0][a_r] = a0.x; As[a_c + 1][a_r] = a0.y;
        As[a_c + 2][a_r] = a0.z; As[a_c + 3][a_r] = a0.w;
        As[a_c + 0][a_r + 64] = a1.x; As[a_c + 1][a_r + 64] = a1.y;
        As[a_c + 2][a_r + 64] = a1.z; As[a_c + 3][a_r + 64] = a1.w;
        *(float4*)&Bs[b_r][b_c]     = b0;
        *(float4*)&Bs[b_r + 8][b_c] = b1;
        __syncthreads();
        #pragma unroll
        for (int kk = 0; kk < 16; kk++) {
            float ar[8], br[8];
            *(float4*)&ar[0] = *(const float4*)&As[kk][ty * 8];
            *(float4*)&ar[4] = *(const float4*)&As[kk][ty * 8 + 4];
            *(float4*)&br[0] = *(const float4*)&Bs[kk][tx * 8];
            *(float4*)&br[4] = *(const float4*)&Bs[kk][tx * 8 + 4];
            #pragma unroll
            for (int i = 0; i < 8; i++)
                #pragma unroll
                for (int j = 0; j < 8; j++)
                    acc[i][j] += ar[i] * br[j];
        }
        __syncthreads();
    }

    float bb[8];
    #pragma unroll
    for (int j = 0; j < 8; j++) bb[j] = bias[col0 + tx * 8 + j];

    #pragma unroll
    for (int i = 0; i < 8; i++) {
        const size_t crow = row0 + ty * 8 + i;
        float* cp = C + crow * (size_t)N + col0 + tx * 8;
        const float* ep = (MODE != 0) ? (extra + crow * (size_t)N + col0 + tx * 8) : nullptr;
        #pragma unroll
        for (int j = 0; j < 8; j++) {
            float t = acc[i][j] + bb[j];
            if (MODE == 1) t += ep[j];
            if (MODE == 2) { float gv = ep[j]; t *= gv / (1.f + __expf(-gv)); }
            cp[j] = t;
        }
    }
}

// ---------------- RoPE / relayout / cache copy ----------------
// q: (b,s,h,d) -> (b,h,s,d), rope, * QK_SCALE
__global__ __launch_bounds__(256) void rope_q_kernel(
    const float* __restrict__ in, const float* __restrict__ cosb,
    const float* __restrict__ sinb, float* __restrict__ out)
{
    int idx = blockIdx.x * 256 + threadIdx.x;        // 2^22 total
    int i = idx & 63;
    int h = (idx >> 6) & 15;
    int s = (idx >> 10) & 2047;
    int b = idx >> 21;
    int pos = PREV_LEN + s;
    float2 v = *(const float2*)(in + ((size_t)((b * S_LEN + s) * HEADS + h) * HD) + 2 * i);
    float c = cosb[pos * 64 + i], sn = sinb[pos * 64 + i];
    float x0 = v.x * c - v.y * sn;
    float x1 = v.x * sn + v.y * c;
    *(float2*)(out + ((size_t)((b * HEADS + h) * S_LEN + s) * HD) + 2 * i) =
        make_float2(x0 * QK_SCALE, x1 * QK_SCALE);
}

// k: (b,s,h,d) -> out_k (b,h,1024+s,d), rope, no scale
__global__ __launch_bounds__(256) void rope_k_kernel(
    const float* __restrict__ in, const float* __restrict__ cosb,
    const float* __restrict__ sinb, float* __restrict__ out)
{
    int idx = blockIdx.x * 256 + threadIdx.x;
    int i = idx & 63;
    int h = (idx >> 6) & 15;
    int s = (idx >> 10) & 2047;
    int b = idx >> 21;
    int pos = PREV_LEN + s;
    float2 v = *(const float2*)(in + ((size_t)((b * S_LEN + s) * HEADS + h) * HD) + 2 * i);
    float c = cosb[pos * 64 + i], sn = sinb[pos * 64 + i];
    float x0 = v.x * c - v.y * sn;
    float x1 = v.x * sn + v.y * c;
    *(float2*)(out + ((size_t)((b * HEADS + h) * T_LEN + PREV_LEN + s) * HD) + 2 * i) =
        make_float2(x0, x1);
}

// v: (b,s,h,d) -> out_v (b,h,1024+s,d)
__global__ __launch_bounds__(256) void copy_v_kernel(
    const float* __restrict__ in, float* __restrict__ out)
{
    int idx = blockIdx.x * 256 + threadIdx.x;        // 2^21 float4s
    int d4 = idx & 31;
    int h = (idx >> 5) & 15;
    int s = (idx >> 9) & 2047;
    int b = idx >> 20;
    float4 v = *(const float4*)(in + ((size_t)((b * S_LEN + s) * HEADS + h) * HD) + d4 * 4);
    *(float4*)(out + ((size_t)((b * HEADS + h) * T_LEN + PREV_LEN + s) * HD) + d4 * 4) = v;
}

// cache (b,h,1024,128) contiguous -> out (b,h,t<1024,128)
__global__ __launch_bounds__(256) void copy_cache_kernel(
    const float* __restrict__ in, float* __restrict__ out)
{
    int idx = blockIdx.x * 256 + threadIdx.x;        // 2^20 float4s
    int bh  = idx >> 15;                             // 32768 f4 per (b,h)
    int rem = idx & 32767;
    float4 v = ((const float4*)in)[idx];
    ((float4*)out)[(size_t)bh * (T_LEN * HD / 4) + rem] = v;
}

// ---------------- flash attention ----------------
#define BM 64
#define BN 64
struct FlashSmem {
    float qs[BM][132];
    float ks[BN][132];
    float vs[BN][132];
    float ps[BM][65];
    float m_s[BM];
    float l_s[BM];
    float a_s[BM];
};

__global__ __launch_bounds__(256) void flash_kernel(
    const float* __restrict__ Q, const float* __restrict__ Kc,
    const float* __restrict__ Vc, float* __restrict__ O)
{
    extern __shared__ char smem_raw[];
    FlashSmem& sm = *reinterpret_cast<FlashSmem*>(smem_raw);
    const int tid = threadIdx.x;
    const int m0 = blockIdx.x * BM;
    const int bh = blockIdx.y;
    const float* qp = Q  + (size_t)bh * S_LEN * HD;
    const float* kp = Kc + (size_t)bh * T_LEN * HD;
    const float* vp = Vc + (size_t)bh * T_LEN * HD;

    // load q tile (pre-scaled by QK_SCALE in rope_q)
    {
        const int lr = tid >> 2;
        const int c0 = (tid & 3) * 32;
        const float4* src = (const float4*)(qp + (size_t)(m0 + lr) * HD + c0);
        #pragma unroll
        for (int u = 0; u < 8; u++)
            *(float4*)&sm.qs[lr][c0 + u * 4] = src[u];
    }
    if (tid < BM) { sm.m_s[tid] = -3e38f; sm.l_s[tid] = 0.f; }

    float acc[32];
    #pragma unroll
    for (int i = 0; i < 32; i++) acc[i] = 0.f;
    const int r = tid >> 2;
    const int dbase = (tid & 3) * 32;
    const int rr = (tid >> 4) * 4;
    const int cc = (tid & 15) * 4;
    const int jend = (PREV_LEN + m0 + BM) / BN;   // exact (all div by 64)
    __syncthreads();

    for (int jt = 0; jt < jend; jt++) {
        const int t0 = jt * BN;
        {
            const int lr = tid >> 2;
            const int c0 = (tid & 3) * 32;
            const float4* ksrc = (const float4*)(kp + (size_t)(t0 + lr) * HD + c0);
            const float4* vsrc = (const float4*)(vp + (size_t)(t0 + lr) * HD + c0);
            #pragma unroll
            for (int u = 0; u < 8; u++) {
                *(float4*)&sm.ks[lr][c0 + u * 4] = ksrc[u];
                *(float4*)&sm.vs[lr][c0 + u * 4] = vsrc[u];
            }
        }
        __syncthreads();

        // scores: 4x4 micro-tile per thread
        float sacc[4][4];
        #pragma unroll
        for (int i = 0; i < 4; i++)
            #pragma unroll
            for (int j = 0; j < 4; j++) sacc[i][j] = 0.f;
        #pragma unroll 8
        for (int k4 = 0; k4 < 32; k4++) {
            float4 qv[4], kv[4];
            #pragma unroll
            for (int i = 0; i < 4; i++) qv[i] = *(const float4*)&sm.qs[rr + i][k4 * 4];
            #pragma unroll
            for (int j = 0; j < 4; j++) kv[j] = *(const float4*)&sm.ks[cc + j][k4 * 4];
            #pragma unroll
            for (int i = 0; i < 4; i++)
                #pragma unroll
                for (int j = 0; j < 4; j++)
                    sacc[i][j] += qv[i].x * kv[j].x + qv[i].y * kv[j].y
                                + qv[i].z * kv[j].z + qv[i].w * kv[j].w;
        }
        #pragma unroll
        for (int i = 0; i < 4; i++) {
            const int trow = m0 + rr + i;
            #pragma unroll
            for (int j = 0; j < 4; j++) {
                const int tcol = t0 + cc + j;
                sm.ps[rr + i][cc + j] = (tcol <= PREV_LEN + trow) ? sacc[i][j] : -3e38f;
            }
        }
        __syncthreads();

        // online softmax, one thread per row
        if (tid < BM) {
            float mold = sm.m_s[tid];
            float mx = mold;
            #pragma unroll 8
            for (int c = 0; c < BN; c++) mx = fmaxf(mx, sm.ps[tid][c]);
            float alpha = __expf(mold - mx);
            float sum = 0.f;
            #pragma unroll 8
            for (int c = 0; c < BN; c++) {
                float p = __expf(sm.ps[tid][c] - mx);
                sm.ps[tid][c] = p;
                sum += p;
            }
            sm.m_s[tid] = mx;
            sm.l_s[tid] = sm.l_s[tid] * alpha + sum;
            sm.a_s[tid] = alpha;
        }
        __syncthreads();

        // acc = acc*alpha + P@V  (thread: row r, 32 d-cols at dbase)
        float alpha = sm.a_s[r];
        #pragma unroll
        for (int i = 0; i < 32; i++) acc[i] *= alpha;
        #pragma unroll 4
        for (int kk = 0; kk < BN; kk++) {
            float p = sm.ps[r][kk];
            const float4* vv = (const float4*)&sm.vs[kk][dbase];
            #pragma unroll
            for (int u = 0; u < 8; u++) {
                float4 v4 = vv[u];
                acc[u * 4 + 0] += p * v4.x;
                acc[u * 4 + 1] += p * v4.y;
                acc[u * 4 + 2] += p * v4.z;
                acc[u * 4 + 3] += p * v4.w;
            }
        }
        __syncthreads();
    }

    const float inv_l = 1.f / sm.l_s[r];
    const int b = bh >> 4, h = bh & 15;
    const int srow = m0 + r;
    float* op = O + ((size_t)(b * S_LEN + srow) * DIM) + h * HD + dbase;
    #pragma unroll
    for (int u = 0; u < 8; u++) {
        *(float4*)(op + u * 4) = make_float4(acc[u * 4 + 0] * inv_l, acc[u * 4 + 1] * inv_l,
                                             acc[u * 4 + 2] * inv_l, acc[u * 4 + 3] * inv_l);
    }
}

// ---------------- launch ----------------
extern "C" void kernel_launch(void* const* d_in, const int* in_sizes, int n_in,
                              void* d_out, int out_size)
{
    const float* x          = (const float*)d_in[0];
    const float* k_cache    = (const float*)d_in[1];
    const float* v_cache    = (const float*)d_in[2];
    const float* attn_norm_w= (const float*)d_in[3];
    const float* ffn_norm_w = (const float*)d_in[4];
    const float* wq = (const float*)d_in[5];
    const float* bq = (const float*)d_in[6];
    const float* wk = (const float*)d_in[7];
    const float* bk = (const float*)d_in[8];
    const float* wv = (const float*)d_in[9];
    const float* bv = (const float*)d_in[10];
    const float* wo = (const float*)d_in[11];
    const float* bo = (const float*)d_in[12];
    const float* w_gate = (const float*)d_in[13];
    const float* b_gate = (const float*)d_in[14];
    const float* w_val  = (const float*)d_in[15];
    const float* b_val  = (const float*)d_in[16];
    const float* w_proj = (const float*)d_in[17];
    const float* b_proj = (const float*)d_in[18];
    const float* fcos   = (const float*)d_in[19];
    const float* fsin   = (const float*)d_in[20];

    float* out_x = (float*)d_out;
    float* out_k = out_x + OUT_X_ELEMS;
    float* out_v = out_k + OUT_KV_ELEMS;

    float *p_h, *p_qt, *p_kt, *p_vt, *p_q, *p_o, *p_x1, *p_h2, *p_g;
    cudaGetSymbolAddress((void**)&p_h,  g_h);
    cudaGetSymbolAddress((void**)&p_qt, g_qt);
    cudaGetSymbolAddress((void**)&p_kt, g_kt);
    cudaGetSymbolAddress((void**)&p_vt, g_vt);
    cudaGetSymbolAddress((void**)&p_q,  g_q);
    cudaGetSymbolAddress((void**)&p_o,  g_o);
    cudaGetSymbolAddress((void**)&p_x1, g_x1);
    cudaGetSymbolAddress((void**)&p_h2, g_h2);
    cudaGetSymbolAddress((void**)&p_g,  g_g);

    const dim3 g16(DIM / 128, ROWS / 128);     // (16, 32)
    const dim3 g64(FF_DIM / 128, ROWS / 128);  // (64, 32)

    // attention block
    rmsnorm_kernel<<<ROWS, 256>>>(x, attn_norm_w, p_h);
    gemm_kernel<0><<<g16, 256>>>(p_h, wq, bq, nullptr, p_qt, ROWS, DIM, DIM);
    gemm_kernel<0><<<g16, 256>>>(p_h, wk, bk, nullptr, p_kt, ROWS, DIM, DIM);
    gemm_kernel<0><<<g16, 256>>>(p_h, wv, bv, nullptr, p_vt, ROWS, DIM, DIM);
    rope_q_kernel<<<16384, 256>>>(p_qt, fcos, fsin, p_q);
    rope_k_kernel<<<16384, 256>>>(p_kt, fcos, fsin, out_k);
    copy_v_kernel<<<8192, 256>>>(p_vt, out_v);
    copy_cache_kernel<<<4096, 256>>>(k_cache, out_k);
    copy_cache_kernel<<<4096, 256>>>(v_cache, out_v);

    cudaFuncSetAttribute(flash_kernel, cudaFuncAttributeMaxDynamicSharedMemorySize,
                         (int)sizeof(FlashSmem));
    flash_kernel<<<dim3(S_LEN / BM, BATCH * HEADS), 256, sizeof(FlashSmem)>>>(
        p_q, out_k, out_v, p_o);

    gemm_kernel<1><<<g16, 256>>>(p_o, wo, bo, x, p_x1, ROWS, DIM, DIM);

    // ffn block
    rmsnorm_kernel<<<ROWS, 256>>>(p_x1, ffn_norm_w, p_h2);
    gemm_kernel<0><<<g64, 256>>>(p_h2, w_gate, b_gate, nullptr, p_g, ROWS, FF_DIM, DIM);
    gemm_kernel<2><<<g64, 256>>>(p_h2, w_val, b_val, p_g, p_g, ROWS, FF_DIM, DIM);
    gemm_kernel<1><<<g16, 256>>>(p_g, w_proj, b_proj, p_x1, out_x, ROWS, DIM, FF_DIM);
}

// round 3
// speedup vs baseline: 1.4146x; 1.4146x over previous
#include <cuda_runtime.h>
#include <cuda_bf16.h>
#include <cstdint>

// ---------------- problem constants ----------------
#define BATCH 2
#define S_LEN 2048
#define PREV_LEN 1024
#define T_LEN 3072
#define DIM 2048
#define HEADS 16
#define HD 128
#define FF_DIM 8192
#define ROWS (BATCH * S_LEN)  // 4096
#define QK_SCALE 0.08838834764831845f

#define OUT_X_ELEMS  (BATCH * S_LEN * DIM)
#define OUT_KV_ELEMS (BATCH * HEADS * T_LEN * HD)

// ================= PTX helpers (all portable: sm_80+, no 'a' features) ====
__device__ __forceinline__ uint32_t smem_u32(const void* p) {
    uint32_t a;
    asm("{ .reg .u64 t; cvta.to.shared.u64 t, %1; cvt.u32.u64 %0, t; }" : "=r"(a) : "l"(p));
    return a;
}
__device__ __forceinline__ void cp_async16(uint32_t smem, const void* g) {
    asm volatile("cp.async.cg.shared.global [%0], [%1], 16;" :: "r"(smem), "l"(g) : "memory");
}
#define CP_COMMIT() asm volatile("cp.async.commit_group;" ::: "memory")
#define CP_WAIT2()  asm volatile("cp.async.wait_group 2;" ::: "memory")

__device__ __forceinline__ void ldsm4(uint32_t* r, uint32_t addr) {
    asm volatile("ldmatrix.sync.aligned.m8n8.x4.shared.b16 {%0,%1,%2,%3}, [%4];"
        : "=r"(r[0]), "=r"(r[1]), "=r"(r[2]), "=r"(r[3]) : "r"(addr));
}
__device__ __forceinline__ void mma_bf16(float* c, const uint32_t* a, uint32_t b0, uint32_t b1) {
    asm volatile(
        "mma.sync.aligned.m16n8k16.row.col.f32.bf16.bf16.f32 "
        "{%0,%1,%2,%3}, {%4,%5,%6,%7}, {%8,%9}, {%0,%1,%2,%3};"
        : "+f"(c[0]), "+f"(c[1]), "+f"(c[2]), "+f"(c[3])
        : "r"(a[0]), "r"(a[1]), "r"(a[2]), "r"(a[3]), "r"(b0), "r"(b1));
}

// ---------------- scratch (device globals) --------
__device__ float g_qt [ROWS * DIM];
__device__ float g_kt [ROWS * DIM];
__device__ float g_vt [ROWS * DIM];
__device__ float g_q  [ROWS * DIM];   // (b,h,s,d)
__device__ float g_x1 [ROWS * DIM];
__device__ float g_g  [ROWS * FF_DIM];
// bf16 hi/lo row-major activations
__device__ __nv_bfloat16 g_hA_hi [ROWS * DIM];
__device__ __nv_bfloat16 g_hA_lo [ROWS * DIM];
__device__ __nv_bfloat16 g_h2_hi [ROWS * DIM];
__device__ __nv_bfloat16 g_h2_lo [ROWS * DIM];
__device__ __nv_bfloat16 g_o_hi  [ROWS * DIM];
__device__ __nv_bfloat16 g_o_lo  [ROWS * DIM];
__device__ __nv_bfloat16 g_gt_hi [ROWS * FF_DIM];
__device__ __nv_bfloat16 g_gt_lo [ROWS * FF_DIM];
// bf16 hi/lo transposed weights [N][K]
__device__ __nv_bfloat16 g_wq_hi [DIM * DIM];
__device__ __nv_bfloat16 g_wq_lo [DIM * DIM];
__device__ __nv_bfloat16 g_wk_hi [DIM * DIM];
__device__ __nv_bfloat16 g_wk_lo [DIM * DIM];
__device__ __nv_bfloat16 g_wv_hi [DIM * DIM];
__device__ __nv_bfloat16 g_wv_lo [DIM * DIM];
__device__ __nv_bfloat16 g_wo_hi [DIM * DIM];
__device__ __nv_bfloat16 g_wo_lo [DIM * DIM];
__device__ __nv_bfloat16 g_wg_hi [DIM * FF_DIM];
__device__ __nv_bfloat16 g_wg_lo [DIM * FF_DIM];
__device__ __nv_bfloat16 g_wv2_hi[DIM * FF_DIM];
__device__ __nv_bfloat16 g_wv2_lo[DIM * FF_DIM];
__device__ __nv_bfloat16 g_wp_hi [FF_DIM * DIM];
__device__ __nv_bfloat16 g_wp_lo [FF_DIM * DIM];

// =====================================================================
// Weight converter + transpose: W[K][N] fp32 -> Wt[N][K] bf16 hi/lo.
// grid (K/32, N/32), 256 threads.
// =====================================================================
__global__ __launch_bounds__(256) void weight_conv_t(
    const float* __restrict__ W, __nv_bfloat16* __restrict__ Thi,
    __nv_bfloat16* __restrict__ Tlo, int N, int K)
{
    __shared__ float tile[32][33];
    const int k0 = blockIdx.x * 32, n0 = blockIdx.y * 32;
    const int tx = threadIdx.x & 31, ty = threadIdx.x >> 5;
    #pragma unroll
    for (int i = 0; i < 4; i++) {
        int k = ty + i * 8;
        tile[k][tx] = W[(size_t)(k0 + k) * N + n0 + tx];
    }
    __syncthreads();
    #pragma unroll
    for (int i = 0; i < 4; i++) {
        int n = ty + i * 8;
        float v = tile[tx][n];
        __nv_bfloat16 h = __float2bfloat16(v);
        Thi[(size_t)(n0 + n) * K + k0 + tx] = h;
        Tlo[(size_t)(n0 + n) * K + k0 + tx] = __float2bfloat16(v - __bfloat162float(h));
    }
}

// =====================================================================
// rmsnorm -> hi/lo bf16 row-major
// =====================================================================
__global__ __launch_bounds__(256) void rmsnorm_split(
    const float* __restrict__ x, const float* __restrict__ w,
    __nv_bfloat16* __restrict__ Ohi, __nv_bfloat16* __restrict__ Olo)
{
    __shared__ float red[256];
    const int tid = threadIdx.x;
    const int m = blockIdx.x;
    const float* xp = x + (size_t)m * DIM + tid * 8;
    float4 a = *(const float4*)xp;
    float4 b = *(const float4*)(xp + 4);
    float s = a.x*a.x + a.y*a.y + a.z*a.z + a.w*a.w
            + b.x*b.x + b.y*b.y + b.z*b.z + b.w*b.w;
    red[tid] = s;
    __syncthreads();
    #pragma unroll
    for (int off = 128; off > 0; off >>= 1) {
        if (tid < off) red[tid] += red[tid + off];
        __syncthreads();
    }
    float scale = rsqrtf(red[0] * (1.0f / DIM) + 1e-6f);
    const float* wp = w + tid * 8;
    float4 wa = *(const float4*)wp;
    float4 wb = *(const float4*)(wp + 4);
    float y[8];
    y[0] = a.x*scale*wa.x; y[1] = a.y*scale*wa.y; y[2] = a.z*scale*wa.z; y[3] = a.w*scale*wa.w;
    y[4] = b.x*scale*wb.x; y[5] = b.y*scale*wb.y; y[6] = b.z*scale*wb.z; y[7] = b.w*scale*wb.w;
    __align__(16) __nv_bfloat16 hv[8], lv[8];
    #pragma unroll
    for (int j = 0; j < 8; j++) {
        __nv_bfloat16 h16 = __float2bfloat16(y[j]);
        hv[j] = h16;
        lv[j] = __float2bfloat16(y[j] - __bfloat162float(h16));
    }
    *(uint4*)(Ohi + (size_t)m * DIM + tid * 8) = *(const uint4*)hv;
    *(uint4*)(Olo + (size_t)m * DIM + tid * 8) = *(const uint4*)lv;
}

// =====================================================================
// HMMA split-bf16 GEMM. CTA 128x128, K-chunk 32, 8 warps, 4-stage cp.async.
// A row-major [M][K] hi/lo bf16; B transposed [N][K] hi/lo bf16 (TN).
// MODE 0: C = A@B + bias            (fp32 out)
// MODE 1: C = A@B + bias + extra    (fp32 out)
// MODE 2: Chi/Clo = split(silu(extra) * (A@B + bias))  (bf16 out)
// =====================================================================
#define GM_STAGES 4
#define GM_STAGE_BYTES 32768
#define GM_SMEM (GM_STAGES * GM_STAGE_BYTES)
#define OFF_AH 0
#define OFF_AL 8192
#define OFF_BH 16384
#define OFF_BL 24576

__device__ __forceinline__ uint32_t swz(int r, int g) {
    return (uint32_t)(r * 64 + ((g ^ ((r >> 1) & 3)) << 4));
}

template<int MODE>
__global__ void __launch_bounds__(256) gemm_mma(
    const __nv_bfloat16* __restrict__ Ahi, const __nv_bfloat16* __restrict__ Alo,
    const __nv_bfloat16* __restrict__ Bhi, const __nv_bfloat16* __restrict__ Blo,
    const float* __restrict__ bias, const float* __restrict__ extra,
    float* __restrict__ C, __nv_bfloat16* __restrict__ Chi, __nv_bfloat16* __restrict__ Clo,
    int M, int N, int K)
{
    extern __shared__ char smraw[];
    const uint32_t sb = smem_u32(smraw);
    const int tid = threadIdx.x;
    const int wid = tid >> 5;
    const int lane = tid & 31;
    const int wm = wid & 1;        // 2 m-groups of 64
    const int wn = wid >> 1;       // 4 n-groups of 32
    const int ntile = blockIdx.x;
    const int mtile = blockIdx.y;
    const int m0 = mtile * 128;
    const int n0 = ntile * 128;
    const int nk = K >> 5;

    // per-thread load coords: 512 16B-chunks per 8KB matrix, 2 per thread
    const int lr = tid >> 2;       // 0..63
    const int lg = tid & 3;        // 0..3

    float acc[4][4][4];
    #pragma unroll
    for (int a = 0; a < 4; a++)
        #pragma unroll
        for (int b = 0; b < 4; b++)
            #pragma unroll
            for (int c = 0; c < 4; c++) acc[a][b][c] = 0.f;

    auto issue_stage = [&](int kc, int slot) {
        const uint32_t st = sb + slot * GM_STAGE_BYTES;
        const int kelem = kc * 32 + lg * 8;
        #pragma unroll
        for (int half = 0; half < 2; half++) {
            const int r = lr + half * 64;
            const uint32_t sw = swz(r, lg);
            cp_async16(st + OFF_AH + sw, Ahi + (size_t)(m0 + r) * K + kelem);
            cp_async16(st + OFF_AL + sw, Alo + (size_t)(m0 + r) * K + kelem);
            cp_async16(st + OFF_BH + sw, Bhi + (size_t)(n0 + r) * K + kelem);
            cp_async16(st + OFF_BL + sw, Blo + (size_t)(n0 + r) * K + kelem);
        }
    };

    // prologue: 3 stages in flight
    issue_stage(0, 0); CP_COMMIT();
    issue_stage(1, 1); CP_COMMIT();
    issue_stage(2, 2); CP_COMMIT();

    for (int kc = 0; kc < nk; kc++) {
        CP_WAIT2();
        __syncthreads();
        if (kc + 3 < nk) issue_stage(kc + 3, (kc + 3) & 3);
        CP_COMMIT();   // empty group when no issue keeps wait-count semantics

        const uint32_t st = sb + (kc & 3) * GM_STAGE_BYTES;
        #pragma unroll
        for (int h = 0; h < 2; h++) {
            uint32_t ah[4][4], al[4][4], bhm[2][4], blm[2][4];
            #pragma unroll
            for (int mi = 0; mi < 4; mi++) {
                const int r = wm * 64 + mi * 16 + (lane & 15);
                const uint32_t sw = swz(r, h * 2 + (lane >> 4));
                ldsm4(ah[mi], st + OFF_AH + sw);
                ldsm4(al[mi], st + OFF_AL + sw);
            }
            #pragma unroll
            for (int nj = 0; nj < 2; nj++) {
                const int r = wn * 32 + nj * 16 + (lane & 15);
                const uint32_t sw = swz(r, h * 2 + (lane >> 4));
                ldsm4(bhm[nj], st + OFF_BH + sw);
                ldsm4(blm[nj], st + OFF_BL + sw);
            }
            // b fragment per n8 tile j: {r[j&1], r[2+(j&1)]} of group j>>1
            #pragma unroll
            for (int mi = 0; mi < 4; mi++)
                #pragma unroll
                for (int j = 0; j < 4; j++)
                    mma_bf16(acc[mi][j], ah[mi], bhm[j >> 1][j & 1], bhm[j >> 1][2 + (j & 1)]);
            #pragma unroll
            for (int mi = 0; mi < 4; mi++)
                #pragma unroll
                for (int j = 0; j < 4; j++)
                    mma_bf16(acc[mi][j], ah[mi], blm[j >> 1][j & 1], blm[j >> 1][2 + (j & 1)]);
            #pragma unroll
            for (int mi = 0; mi < 4; mi++)
                #pragma unroll
                for (int j = 0; j < 4; j++)
                    mma_bf16(acc[mi][j], al[mi], bhm[j >> 1][j & 1], bhm[j >> 1][2 + (j & 1)]);
        }
        __syncthreads();
    }

    // ---------------- epilogue ----------------
    const int mb = m0 + wm * 64;
    const int nb = n0 + wn * 32;
    #pragma unroll
    for (int mi = 0; mi < 4; mi++) {
        #pragma unroll
        for (int j = 0; j < 4; j++) {
            const int row = mb + mi * 16 + (lane >> 2);
            const int col = nb + j * 8 + (lane & 3) * 2;
            const float b0 = bias[col], b1 = bias[col + 1];
            #pragma unroll
            for (int half = 0; half < 2; half++) {
                const int rr = row + half * 8;
                float v0 = acc[mi][j][half * 2 + 0] + b0;
                float v1 = acc[mi][j][half * 2 + 1] + b1;
                if (MODE == 1) {
                    const float* ep = extra + (size_t)rr * N + col;
                    v0 += ep[0]; v1 += ep[1];
                }
                if (MODE == 2) {
                    const float* ep = extra + (size_t)rr * N + col;
                    float g0 = ep[0], g1 = ep[1];
                    v0 *= g0 / (1.f + __expf(-g0));
                    v1 *= g1 / (1.f + __expf(-g1));
                    __nv_bfloat16 h0 = __float2bfloat16(v0);
                    __nv_bfloat16 h1 = __float2bfloat16(v1);
                    __nv_bfloat162 hh, ll;
                    hh.x = h0; hh.y = h1;
                    ll.x = __float2bfloat16(v0 - __bfloat162float(h0));
                    ll.y = __float2bfloat16(v1 - __bfloat162float(h1));
                    *(__nv_bfloat162*)(Chi + (size_t)rr * N + col) = hh;
                    *(__nv_bfloat162*)(Clo + (size_t)rr * N + col) = ll;
                } else {
                    *(float2*)(C + (size_t)rr * N + col) = make_float2(v0, v1);
                }
            }
        }
    }
}

// ---------------- RoPE / relayout / cache copy (proven) -------
__global__ __launch_bounds__(256) void rope_q_kernel(
    const float* __restrict__ in, const float* __restrict__ cosb,
    const float* __restrict__ sinb, float* __restrict__ out)
{
    int idx = blockIdx.x * 256 + threadIdx.x;
    int i = idx & 63;
    int h = (idx >> 6) & 15;
    int s = (idx >> 10) & 2047;
    int b = idx >> 21;
    int pos = PREV_LEN + s;
    float2 v = *(const float2*)(in + ((size_t)((b * S_LEN + s) * HEADS + h) * HD) + 2 * i);
    float c = cosb[pos * 64 + i], sn = sinb[pos * 64 + i];
    float x0 = v.x * c - v.y * sn;
    float x1 = v.x * sn + v.y * c;
    *(float2*)(out + ((size_t)((b * HEADS + h) * S_LEN + s) * HD) + 2 * i) =
        make_float2(x0 * QK_SCALE, x1 * QK_SCALE);
}

__global__ __launch_bounds__(256) void rope_k_kernel(
    const float* __restrict__ in, const float* __restrict__ cosb,
    const float* __restrict__ sinb, float* __restrict__ out)
{
    int idx = blockIdx.x * 256 + threadIdx.x;
    int i = idx & 63;
    int h = (idx >> 6) & 15;
    int s = (idx >> 10) & 2047;
    int b = idx >> 21;
    int pos = PREV_LEN + s;
    float2 v = *(const float2*)(in + ((size_t)((b * S_LEN + s) * HEADS + h) * HD) + 2 * i);
    float c = cosb[pos * 64 + i], sn = sinb[pos * 64 + i];
    float x0 = v.x * c - v.y * sn;
    float x1 = v.x * sn + v.y * c;
    *(float2*)(out + ((size_t)((b * HEADS + h) * T_LEN + PREV_LEN + s) * HD) + 2 * i) =
        make_float2(x0, x1);
}

__global__ __launch_bounds__(256) void copy_v_kernel(
    const float* __restrict__ in, float* __restrict__ out)
{
    int idx = blockIdx.x * 256 + threadIdx.x;
    int d4 = idx & 31;
    int h = (idx >> 5) & 15;
    int s = (idx >> 9) & 2047;
    int b = idx >> 20;
    float4 v = *(const float4*)(in + ((size_t)((b * S_LEN + s) * HEADS + h) * HD) + d4 * 4);
    *(float4*)(out + ((size_t)((b * HEADS + h) * T_LEN + PREV_LEN + s) * HD) + d4 * 4) = v;
}

__global__ __launch_bounds__(256) void copy_cache_kernel(
    const float* __restrict__ in, float* __restrict__ out)
{
    int idx = blockIdx.x * 256 + threadIdx.x;
    int bh  = idx >> 15;
    int rem = idx & 32767;
    float4 v = ((const float4*)in)[idx];
    ((float4*)out)[(size_t)bh * (T_LEN * HD / 4) + rem] = v;
}

// ---------------- flash attention (fp32, proven) ----------------
#define BM 64
#define BN 64
struct FlashSmem {
    float qs[BM][132];
    float ks[BN][132];
    float vs[BN][132];
    float ps[BM][65];
    float m_s[BM];
    float l_s[BM];
    float a_s[BM];
};

__global__ __launch_bounds__(256) void flash_kernel(
    const float* __restrict__ Q, const float* __restrict__ Kc,
    const float* __restrict__ Vc, __nv_bfloat16* __restrict__ Ohi,
    __nv_bfloat16* __restrict__ Olo)
{
    extern __shared__ char smem_raw[];
    FlashSmem& sm = *reinterpret_cast<FlashSmem*>(smem_raw);
    const int tid = threadIdx.x;
    const int m0 = blockIdx.x * BM;
    const int bh = blockIdx.y;
    const float* qp = Q  + (size_t)bh * S_LEN * HD;
    const float* kp = Kc + (size_t)bh * T_LEN * HD;
    const float* vp = Vc + (size_t)bh * T_LEN * HD;

    {
        const int lr = tid >> 2;
        const int c0 = (tid & 3) * 32;
        const float4* src = (const float4*)(qp + (size_t)(m0 + lr) * HD + c0);
        #pragma unroll
        for (int u = 0; u < 8; u++)
            *(float4*)&sm.qs[lr][c0 + u * 4] = src[u];
    }
    if (tid < BM) { sm.m_s[tid] = -3e38f; sm.l_s[tid] = 0.f; }

    float acc[32];
    #pragma unroll
    for (int i = 0; i < 32; i++) acc[i] = 0.f;
    const int r = tid >> 2;
    const int dbase = (tid & 3) * 32;
    const int rr = (tid >> 4) * 4;
    const int cc = (tid & 15) * 4;
    const int jend = (PREV_LEN + m0 + BM) / BN;
    __syncthreads();

    for (int jt = 0; jt < jend; jt++) {
        const int t0 = jt * BN;
        {
            const int lr = tid >> 2;
            const int c0 = (tid & 3) * 32;
            const float4* ksrc = (const float4*)(kp + (size_t)(t0 + lr) * HD + c0);
            const float4* vsrc = (const float4*)(vp + (size_t)(t0 + lr) * HD + c0);
            #pragma unroll
            for (int u = 0; u < 8; u++) {
                *(float4*)&sm.ks[lr][c0 + u * 4] = ksrc[u];
                *(float4*)&sm.vs[lr][c0 + u * 4] = vsrc[u];
            }
        }
        __syncthreads();

        float sacc[4][4];
        #pragma unroll
        for (int i = 0; i < 4; i++)
            #pragma unroll
            for (int j = 0; j < 4; j++) sacc[i][j] = 0.f;
        #pragma unroll 8
        for (int k4 = 0; k4 < 32; k4++) {
            float4 qv[4], kv[4];
            #pragma unroll
            for (int i = 0; i < 4; i++) qv[i] = *(const float4*)&sm.qs[rr + i][k4 * 4];
            #pragma unroll
            for (int j = 0; j < 4; j++) kv[j] = *(const float4*)&sm.ks[cc + j][k4 * 4];
            #pragma unroll
            for (int i = 0; i < 4; i++)
                #pragma unroll
                for (int j = 0; j < 4; j++)
                    sacc[i][j] += qv[i].x * kv[j].x + qv[i].y * kv[j].y
                                + qv[i].z * kv[j].z + qv[i].w * kv[j].w;
        }
        #pragma unroll
        for (int i = 0; i < 4; i++) {
            const int trow = m0 + rr + i;
            #pragma unroll
            for (int j = 0; j < 4; j++) {
                const int tcol = t0 + cc + j;
                sm.ps[rr + i][cc + j] = (tcol <= PREV_LEN + trow) ? sacc[i][j] : -3e38f;
            }
        }
        __syncthreads();

        if (tid < BM) {
            float mold = sm.m_s[tid];
            float mx = mold;
            #pragma unroll 8
            for (int c = 0; c < BN; c++) mx = fmaxf(mx, sm.ps[tid][c]);
            float alpha = __expf(mold - mx);
            float sum = 0.f;
            #pragma unroll 8
            for (int c = 0; c < BN; c++) {
                float p = __expf(sm.ps[tid][c] - mx);
                sm.ps[tid][c] = p;
                sum += p;
            }
            sm.m_s[tid] = mx;
            sm.l_s[tid] = sm.l_s[tid] * alpha + sum;
            sm.a_s[tid] = alpha;
        }
        __syncthreads();

        float alpha = sm.a_s[r];
        #pragma unroll
        for (int i = 0; i < 32; i++) acc[i] *= alpha;
        #pragma unroll 4
        for (int kk = 0; kk < BN; kk++) {
            float p = sm.ps[r][kk];
            const float4* vv = (const float4*)&sm.vs[kk][dbase];
            #pragma unroll
            for (int u = 0; u < 8; u++) {
                float4 v4 = vv[u];
                acc[u * 4 + 0] += p * v4.x;
                acc[u * 4 + 1] += p * v4.y;
                acc[u * 4 + 2] += p * v4.z;
                acc[u * 4 + 3] += p * v4.w;
            }
        }
        __syncthreads();
    }

    const float inv_l = 1.f / sm.l_s[r];
    const int b = bh >> 4, h = bh & 15;
    const int srow = m0 + r;
    const size_t mrow = (size_t)(b * S_LEN + srow) * DIM + h * HD + dbase;
    #pragma unroll
    for (int u = 0; u < 4; u++) {
        __align__(16) __nv_bfloat16 hv[8], lv[8];
        #pragma unroll
        for (int j = 0; j < 8; j++) {
            float t = acc[u * 8 + j] * inv_l;
            __nv_bfloat16 h16 = __float2bfloat16(t);
            hv[j] = h16;
            lv[j] = __float2bfloat16(t - __bfloat162float(h16));
        }
        *(uint4*)(Ohi + mrow + u * 8) = *(const uint4*)hv;
        *(uint4*)(Olo + mrow + u * 8) = *(const uint4*)lv;
    }
}

// ---------------- launch ----------------
extern "C" void kernel_launch(void* const* d_in, const int* in_sizes, int n_in,
                              void* d_out, int out_size)
{
    const float* x          = (const float*)d_in[0];
    const float* k_cache    = (const float*)d_in[1];
    const float* v_cache    = (const float*)d_in[2];
    const float* attn_norm_w= (const float*)d_in[3];
    const float* ffn_norm_w = (const float*)d_in[4];
    const float* wq = (const float*)d_in[5];
    const float* bq = (const float*)d_in[6];
    const float* wk = (const float*)d_in[7];
    const float* bk = (const float*)d_in[8];
    const float* wv = (const float*)d_in[9];
    const float* bv = (const float*)d_in[10];
    const float* wo = (const float*)d_in[11];
    const float* bo = (const float*)d_in[12];
    const float* w_gate = (const float*)d_in[13];
    const float* b_gate = (const float*)d_in[14];
    const float* w_val  = (const float*)d_in[15];
    const float* b_val  = (const float*)d_in[16];
    const float* w_proj = (const float*)d_in[17];
    const float* b_proj = (const float*)d_in[18];
    const float* fcos   = (const float*)d_in[19];
    const float* fsin   = (const float*)d_in[20];

    float* out_x = (float*)d_out;
    float* out_k = out_x + OUT_X_ELEMS;
    float* out_v = out_k + OUT_KV_ELEMS;

    float *p_qt, *p_kt, *p_vt, *p_q, *p_x1, *p_g;
    __nv_bfloat16 *p_hA_hi, *p_hA_lo, *p_h2_hi, *p_h2_lo, *p_o_hi, *p_o_lo, *p_gt_hi, *p_gt_lo;
    __nv_bfloat16 *p_wq_hi, *p_wq_lo, *p_wk_hi, *p_wk_lo, *p_wv_hi, *p_wv_lo, *p_wo_hi, *p_wo_lo;
    __nv_bfloat16 *p_wg_hi, *p_wg_lo, *p_wv2_hi, *p_wv2_lo, *p_wp_hi, *p_wp_lo;

    cudaGetSymbolAddress((void**)&p_qt, g_qt);
    cudaGetSymbolAddress((void**)&p_kt, g_kt);
    cudaGetSymbolAddress((void**)&p_vt, g_vt);
    cudaGetSymbolAddress((void**)&p_q,  g_q);
    cudaGetSymbolAddress((void**)&p_x1, g_x1);
    cudaGetSymbolAddress((void**)&p_g,  g_g);
    cudaGetSymbolAddress((void**)&p_hA_hi, g_hA_hi);
    cudaGetSymbolAddress((void**)&p_hA_lo, g_hA_lo);
    cudaGetSymbolAddress((void**)&p_h2_hi, g_h2_hi);
    cudaGetSymbolAddress((void**)&p_h2_lo, g_h2_lo);
    cudaGetSymbolAddress((void**)&p_o_hi,  g_o_hi);
    cudaGetSymbolAddress((void**)&p_o_lo,  g_o_lo);
    cudaGetSymbolAddress((void**)&p_gt_hi, g_gt_hi);
    cudaGetSymbolAddress((void**)&p_gt_lo, g_gt_lo);
    cudaGetSymbolAddress((void**)&p_wq_hi, g_wq_hi);
    cudaGetSymbolAddress((void**)&p_wq_lo, g_wq_lo);
    cudaGetSymbolAddress((void**)&p_wk_hi, g_wk_hi);
    cudaGetSymbolAddress((void**)&p_wk_lo, g_wk_lo);
    cudaGetSymbolAddress((void**)&p_wv_hi, g_wv_hi);
    cudaGetSymbolAddress((void**)&p_wv_lo, g_wv_lo);
    cudaGetSymbolAddress((void**)&p_wo_hi, g_wo_hi);
    cudaGetSymbolAddress((void**)&p_wo_lo, g_wo_lo);
    cudaGetSymbolAddress((void**)&p_wg_hi, g_wg_hi);
    cudaGetSymbolAddress((void**)&p_wg_lo, g_wg_lo);
    cudaGetSymbolAddress((void**)&p_wv2_hi, g_wv2_hi);
    cudaGetSymbolAddress((void**)&p_wv2_lo, g_wv2_lo);
    cudaGetSymbolAddress((void**)&p_wp_hi, g_wp_hi);
    cudaGetSymbolAddress((void**)&p_wp_lo, g_wp_lo);

    cudaFuncSetAttribute(gemm_mma<0>, cudaFuncAttributeMaxDynamicSharedMemorySize, GM_SMEM);
    cudaFuncSetAttribute(gemm_mma<1>, cudaFuncAttributeMaxDynamicSharedMemorySize, GM_SMEM);
    cudaFuncSetAttribute(gemm_mma<2>, cudaFuncAttributeMaxDynamicSharedMemorySize, GM_SMEM);
    cudaFuncSetAttribute(flash_kernel, cudaFuncAttributeMaxDynamicSharedMemorySize, (int)sizeof(FlashSmem));

    // ---- weight conversion + transpose ----
    weight_conv_t<<<dim3(64, 64), 256>>>(wq, p_wq_hi, p_wq_lo, DIM, DIM);
    weight_conv_t<<<dim3(64, 64), 256>>>(wk, p_wk_hi, p_wk_lo, DIM, DIM);
    weight_conv_t<<<dim3(64, 64), 256>>>(wv, p_wv_hi, p_wv_lo, DIM, DIM);
    weight_conv_t<<<dim3(64, 64), 256>>>(wo, p_wo_hi, p_wo_lo, DIM, DIM);
    weight_conv_t<<<dim3(64, 256), 256>>>(w_gate, p_wg_hi,  p_wg_lo,  FF_DIM, DIM);
    weight_conv_t<<<dim3(64, 256), 256>>>(w_val,  p_wv2_hi, p_wv2_lo, FF_DIM, DIM);
    weight_conv_t<<<dim3(256, 64), 256>>>(w_proj, p_wp_hi,  p_wp_lo,  DIM, FF_DIM);

    // ---- attention block ----
    rmsnorm_split<<<ROWS, 256>>>(x, attn_norm_w, p_hA_hi, p_hA_lo);
    gemm_mma<0><<<dim3(16, 32), 256, GM_SMEM>>>(
        p_hA_hi, p_hA_lo, p_wq_hi, p_wq_lo, bq, nullptr, p_qt, nullptr, nullptr, ROWS, DIM, DIM);
    gemm_mma<0><<<dim3(16, 32), 256, GM_SMEM>>>(
        p_hA_hi, p_hA_lo, p_wk_hi, p_wk_lo, bk, nullptr, p_kt, nullptr, nullptr, ROWS, DIM, DIM);
    gemm_mma<0><<<dim3(16, 32), 256, GM_SMEM>>>(
        p_hA_hi, p_hA_lo, p_wv_hi, p_wv_lo, bv, nullptr, p_vt, nullptr, nullptr, ROWS, DIM, DIM);

    rope_q_kernel<<<16384, 256>>>(p_qt, fcos, fsin, p_q);
    rope_k_kernel<<<16384, 256>>>(p_kt, fcos, fsin, out_k);
    copy_v_kernel<<<8192, 256>>>(p_vt, out_v);
    copy_cache_kernel<<<4096, 256>>>(k_cache, out_k);
    copy_cache_kernel<<<4096, 256>>>(v_cache, out_v);

    flash_kernel<<<dim3(S_LEN / BM, BATCH * HEADS), 256, sizeof(FlashSmem)>>>(
        p_q, out_k, out_v, p_o_hi, p_o_lo);

    gemm_mma<1><<<dim3(16, 32), 256, GM_SMEM>>>(
        p_o_hi, p_o_lo, p_wo_hi, p_wo_lo, bo, x, p_x1, nullptr, nullptr, ROWS, DIM, DIM);

    // ---- ffn block ----
    rmsnorm_split<<<ROWS, 256>>>(p_x1, ffn_norm_w, p_h2_hi, p_h2_lo);
    gemm_mma<0><<<dim3(64, 32), 256, GM_SMEM>>>(
        p_h2_hi, p_h2_lo, p_wg_hi, p_wg_lo, b_gate, nullptr, p_g, nullptr, nullptr, ROWS, FF_DIM, DIM);
    gemm_mma<2><<<dim3(64, 32), 256, GM_SMEM>>>(
        p_h2_hi, p_h2_lo, p_wv2_hi, p_wv2_lo, b_val, p_g, nullptr, p_gt_hi, p_gt_lo, ROWS, FF_DIM, DIM);
    gemm_mma<1><<<dim3(16, 32), 256, GM_SMEM>>>(
        p_gt_hi, p_gt_lo, p_wp_hi, p_wp_lo, b_proj, p_x1, out_x, nullptr, nullptr, ROWS, DIM, FF_DIM);
}

// round 4
// speedup vs baseline: 3.8677x; 2.7341x over previous
#include <cuda_runtime.h>
#include <cuda_bf16.h>
#include <cstdint>

// ---------------- problem constants ----------------
#define BATCH 2
#define S_LEN 2048
#define PREV_LEN 1024
#define T_LEN 3072
#define DIM 2048
#define HEADS 16
#define HD 128
#define FF_DIM 8192
#define ROWS (BATCH * S_LEN)  // 4096
#define QK_SCALE 0.08838834764831845f

#define OUT_X_ELEMS  (BATCH * S_LEN * DIM)
#define OUT_KV_ELEMS (BATCH * HEADS * T_LEN * HD)

// ================= PTX helpers (portable sm_80+) ====
__device__ __forceinline__ uint32_t smem_u32(const void* p) {
    uint32_t a;
    asm("{ .reg .u64 t; cvta.to.shared.u64 t, %1; cvt.u32.u64 %0, t; }" : "=r"(a) : "l"(p));
    return a;
}
__device__ __forceinline__ void cp_async16(uint32_t smem, const void* g) {
    asm volatile("cp.async.cg.shared.global [%0], [%1], 16;" :: "r"(smem), "l"(g) : "memory");
}
#define CP_COMMIT() asm volatile("cp.async.commit_group;" ::: "memory")
#define CP_WAIT2()  asm volatile("cp.async.wait_group 2;" ::: "memory")
#define CP_WAIT1()  asm volatile("cp.async.wait_group 1;" ::: "memory")

__device__ __forceinline__ void ldsm4(uint32_t* r, uint32_t addr) {
    asm volatile("ldmatrix.sync.aligned.m8n8.x4.shared.b16 {%0,%1,%2,%3}, [%4];"
        : "=r"(r[0]), "=r"(r[1]), "=r"(r[2]), "=r"(r[3]) : "r"(addr));
}
__device__ __forceinline__ void ldsm4t(uint32_t* r, uint32_t addr) {
    asm volatile("ldmatrix.sync.aligned.m8n8.x4.trans.shared.b16 {%0,%1,%2,%3}, [%4];"
        : "=r"(r[0]), "=r"(r[1]), "=r"(r[2]), "=r"(r[3]) : "r"(addr));
}
__device__ __forceinline__ void mma_bf16(float* c, const uint32_t* a, uint32_t b0, uint32_t b1) {
    asm volatile(
        "mma.sync.aligned.m16n8k16.row.col.f32.bf16.bf16.f32 "
        "{%0,%1,%2,%3}, {%4,%5,%6,%7}, {%8,%9}, {%0,%1,%2,%3};"
        : "+f"(c[0]), "+f"(c[1]), "+f"(c[2]), "+f"(c[3])
        : "r"(a[0]), "r"(a[1]), "r"(a[2]), "r"(a[3]), "r"(b0), "r"(b1));
}
__device__ __forceinline__ uint32_t pack_bf16(float a, float b) {
    __nv_bfloat162 t = __floats2bfloat162_rn(a, b);
    return *(uint32_t*)&t;
}
__device__ __forceinline__ void split_store2(
    __nv_bfloat16* Hi, __nv_bfloat16* Lo, size_t off, float a, float b)
{
    __nv_bfloat16 ha = __float2bfloat16(a), hb = __float2bfloat16(b);
    __nv_bfloat162 hh; hh.x = ha; hh.y = hb;
    __nv_bfloat162 ll;
    ll.x = __float2bfloat16(a - __bfloat162float(ha));
    ll.y = __float2bfloat16(b - __bfloat162float(hb));
    *(__nv_bfloat162*)(Hi + off) = hh;
    *(__nv_bfloat162*)(Lo + off) = ll;
}

// ---------------- scratch (device globals) --------
__device__ float g_qt [ROWS * DIM];
__device__ float g_kt [ROWS * DIM];
__device__ float g_vt [ROWS * DIM];
__device__ float g_x1 [ROWS * DIM];
__device__ float g_g  [ROWS * FF_DIM];
// bf16 hi/lo row-major activations
__device__ __nv_bfloat16 g_hA_hi [ROWS * DIM];
__device__ __nv_bfloat16 g_hA_lo [ROWS * DIM];
__device__ __nv_bfloat16 g_h2_hi [ROWS * DIM];
__device__ __nv_bfloat16 g_h2_lo [ROWS * DIM];
__device__ __nv_bfloat16 g_o_hi  [ROWS * DIM];
__device__ __nv_bfloat16 g_o_lo  [ROWS * DIM];
__device__ __nv_bfloat16 g_gt_hi [ROWS * FF_DIM];
__device__ __nv_bfloat16 g_gt_lo [ROWS * FF_DIM];
// bf16 attention operands (b,h,s/t,d)
__device__ __nv_bfloat16 g_q16h [ROWS * DIM];
__device__ __nv_bfloat16 g_q16l [ROWS * DIM];
__device__ __nv_bfloat16 g_k16h [OUT_KV_ELEMS];
__device__ __nv_bfloat16 g_k16l [OUT_KV_ELEMS];
__device__ __nv_bfloat16 g_v16  [OUT_KV_ELEMS];
// bf16 hi/lo transposed weights [N][K]
__device__ __nv_bfloat16 g_wq_hi [DIM * DIM];
__device__ __nv_bfloat16 g_wq_lo [DIM * DIM];
__device__ __nv_bfloat16 g_wk_hi [DIM * DIM];
__device__ __nv_bfloat16 g_wk_lo [DIM * DIM];
__device__ __nv_bfloat16 g_wv_hi [DIM * DIM];
__device__ __nv_bfloat16 g_wv_lo [DIM * DIM];
__device__ __nv_bfloat16 g_wo_hi [DIM * DIM];
__device__ __nv_bfloat16 g_wo_lo [DIM * DIM];
__device__ __nv_bfloat16 g_wg_hi [DIM * FF_DIM];
__device__ __nv_bfloat16 g_wg_lo [DIM * FF_DIM];
__device__ __nv_bfloat16 g_wv2_hi[DIM * FF_DIM];
__device__ __nv_bfloat16 g_wv2_lo[DIM * FF_DIM];
__device__ __nv_bfloat16 g_wp_hi [FF_DIM * DIM];
__device__ __nv_bfloat16 g_wp_lo [FF_DIM * DIM];

// =====================================================================
// Weight converter + transpose: W[K][N] fp32 -> Wt[N][K] bf16 hi/lo.
// =====================================================================
__global__ __launch_bounds__(256) void weight_conv_t(
    const float* __restrict__ W, __nv_bfloat16* __restrict__ Thi,
    __nv_bfloat16* __restrict__ Tlo, int N, int K)
{
    __shared__ float tile[32][33];
    const int k0 = blockIdx.x * 32, n0 = blockIdx.y * 32;
    const int tx = threadIdx.x & 31, ty = threadIdx.x >> 5;
    #pragma unroll
    for (int i = 0; i < 4; i++) {
        int k = ty + i * 8;
        tile[k][tx] = W[(size_t)(k0 + k) * N + n0 + tx];
    }
    __syncthreads();
    #pragma unroll
    for (int i = 0; i < 4; i++) {
        int n = ty + i * 8;
        float v = tile[tx][n];
        __nv_bfloat16 h = __float2bfloat16(v);
        Thi[(size_t)(n0 + n) * K + k0 + tx] = h;
        Tlo[(size_t)(n0 + n) * K + k0 + tx] = __float2bfloat16(v - __bfloat162float(h));
    }
}

// =====================================================================
// rmsnorm -> hi/lo bf16 row-major
// =====================================================================
__global__ __launch_bounds__(256) void rmsnorm_split(
    const float* __restrict__ x, const float* __restrict__ w,
    __nv_bfloat16* __restrict__ Ohi, __nv_bfloat16* __restrict__ Olo)
{
    __shared__ float red[256];
    const int tid = threadIdx.x;
    const int m = blockIdx.x;
    const float* xp = x + (size_t)m * DIM + tid * 8;
    float4 a = *(const float4*)xp;
    float4 b = *(const float4*)(xp + 4);
    float s = a.x*a.x + a.y*a.y + a.z*a.z + a.w*a.w
            + b.x*b.x + b.y*b.y + b.z*b.z + b.w*b.w;
    red[tid] = s;
    __syncthreads();
    #pragma unroll
    for (int off = 128; off > 0; off >>= 1) {
        if (tid < off) red[tid] += red[tid + off];
        __syncthreads();
    }
    float scale = rsqrtf(red[0] * (1.0f / DIM) + 1e-6f);
    const float* wp = w + tid * 8;
    float4 wa = *(const float4*)wp;
    float4 wb = *(const float4*)(wp + 4);
    float y[8];
    y[0] = a.x*scale*wa.x; y[1] = a.y*scale*wa.y; y[2] = a.z*scale*wa.z; y[3] = a.w*scale*wa.w;
    y[4] = b.x*scale*wb.x; y[5] = b.y*scale*wb.y; y[6] = b.z*scale*wb.z; y[7] = b.w*scale*wb.w;
    __align__(16) __nv_bfloat16 hv[8], lv[8];
    #pragma unroll
    for (int j = 0; j < 8; j++) {
        __nv_bfloat16 h16 = __float2bfloat16(y[j]);
        hv[j] = h16;
        lv[j] = __float2bfloat16(y[j] - __bfloat162float(h16));
    }
    *(uint4*)(Ohi + (size_t)m * DIM + tid * 8) = *(const uint4*)hv;
    *(uint4*)(Olo + (size_t)m * DIM + tid * 8) = *(const uint4*)lv;
}

// =====================================================================
// HMMA split-bf16 GEMM (unchanged from passing round).
// =====================================================================
#define GM_STAGES 4
#define GM_STAGE_BYTES 32768
#define GM_SMEM (GM_STAGES * GM_STAGE_BYTES)
#define OFF_AH 0
#define OFF_AL 8192
#define OFF_BH 16384
#define OFF_BL 24576

__device__ __forceinline__ uint32_t swz(int r, int g) {
    return (uint32_t)(r * 64 + ((g ^ ((r >> 1) & 3)) << 4));
}

template<int MODE>
__global__ void __launch_bounds__(256) gemm_mma(
    const __nv_bfloat16* __restrict__ Ahi, const __nv_bfloat16* __restrict__ Alo,
    const __nv_bfloat16* __restrict__ Bhi, const __nv_bfloat16* __restrict__ Blo,
    const float* __restrict__ bias, const float* __restrict__ extra,
    float* __restrict__ C, __nv_bfloat16* __restrict__ Chi, __nv_bfloat16* __restrict__ Clo,
    int M, int N, int K)
{
    extern __shared__ char smraw[];
    const uint32_t sb = smem_u32(smraw);
    const int tid = threadIdx.x;
    const int wid = tid >> 5;
    const int lane = tid & 31;
    const int wm = wid & 1;
    const int wn = wid >> 1;
    const int ntile = blockIdx.x;
    const int mtile = blockIdx.y;
    const int m0 = mtile * 128;
    const int n0 = ntile * 128;
    const int nk = K >> 5;

    const int lr = tid >> 2;
    const int lg = tid & 3;

    float acc[4][4][4];
    #pragma unroll
    for (int a = 0; a < 4; a++)
        #pragma unroll
        for (int b = 0; b < 4; b++)
            #pragma unroll
            for (int c = 0; c < 4; c++) acc[a][b][c] = 0.f;

    auto issue_stage = [&](int kc, int slot) {
        const uint32_t st = sb + slot * GM_STAGE_BYTES;
        const int kelem = kc * 32 + lg * 8;
        #pragma unroll
        for (int half = 0; half < 2; half++) {
            const int r = lr + half * 64;
            const uint32_t sw = swz(r, lg);
            cp_async16(st + OFF_AH + sw, Ahi + (size_t)(m0 + r) * K + kelem);
            cp_async16(st + OFF_AL + sw, Alo + (size_t)(m0 + r) * K + kelem);
            cp_async16(st + OFF_BH + sw, Bhi + (size_t)(n0 + r) * K + kelem);
            cp_async16(st + OFF_BL + sw, Blo + (size_t)(n0 + r) * K + kelem);
        }
    };

    issue_stage(0, 0); CP_COMMIT();
    issue_stage(1, 1); CP_COMMIT();
    issue_stage(2, 2); CP_COMMIT();

    for (int kc = 0; kc < nk; kc++) {
        CP_WAIT2();
        __syncthreads();
        if (kc + 3 < nk) issue_stage(kc + 3, (kc + 3) & 3);
        CP_COMMIT();

        const uint32_t st = sb + (kc & 3) * GM_STAGE_BYTES;
        #pragma unroll
        for (int h = 0; h < 2; h++) {
            uint32_t ah[4][4], al[4][4], bhm[2][4], blm[2][4];
            #pragma unroll
            for (int mi = 0; mi < 4; mi++) {
                const int r = wm * 64 + mi * 16 + (lane & 15);
                const uint32_t sw = swz(r, h * 2 + (lane >> 4));
                ldsm4(ah[mi], st + OFF_AH + sw);
                ldsm4(al[mi], st + OFF_AL + sw);
            }
            #pragma unroll
            for (int nj = 0; nj < 2; nj++) {
                const int r = wn * 32 + nj * 16 + (lane & 15);
                const uint32_t sw = swz(r, h * 2 + (lane >> 4));
                ldsm4(bhm[nj], st + OFF_BH + sw);
                ldsm4(blm[nj], st + OFF_BL + sw);
            }
            #pragma unroll
            for (int mi = 0; mi < 4; mi++)
                #pragma unroll
                for (int j = 0; j < 4; j++)
                    mma_bf16(acc[mi][j], ah[mi], bhm[j >> 1][j & 1], bhm[j >> 1][2 + (j & 1)]);
            #pragma unroll
            for (int mi = 0; mi < 4; mi++)
                #pragma unroll
                for (int j = 0; j < 4; j++)
                    mma_bf16(acc[mi][j], ah[mi], blm[j >> 1][j & 1], blm[j >> 1][2 + (j & 1)]);
            #pragma unroll
            for (int mi = 0; mi < 4; mi++)
                #pragma unroll
                for (int j = 0; j < 4; j++)
                    mma_bf16(acc[mi][j], al[mi], bhm[j >> 1][j & 1], bhm[j >> 1][2 + (j & 1)]);
        }
        __syncthreads();
    }

    const int mb = m0 + wm * 64;
    const int nb = n0 + wn * 32;
    #pragma unroll
    for (int mi = 0; mi < 4; mi++) {
        #pragma unroll
        for (int j = 0; j < 4; j++) {
            const int row = mb + mi * 16 + (lane >> 2);
            const int col = nb + j * 8 + (lane & 3) * 2;
            const float b0 = bias[col], b1 = bias[col + 1];
            #pragma unroll
            for (int half = 0; half < 2; half++) {
                const int rr = row + half * 8;
                float v0 = acc[mi][j][half * 2 + 0] + b0;
                float v1 = acc[mi][j][half * 2 + 1] + b1;
                if (MODE == 1) {
                    const float* ep = extra + (size_t)rr * N + col;
                    v0 += ep[0]; v1 += ep[1];
                }
                if (MODE == 2) {
                    const float* ep = extra + (size_t)rr * N + col;
                    float g0 = ep[0], g1 = ep[1];
                    v0 *= g0 / (1.f + __expf(-g0));
                    v1 *= g1 / (1.f + __expf(-g1));
                    split_store2(Chi, Clo, (size_t)rr * N + col, v0, v1);
                } else {
                    *(float2*)(C + (size_t)rr * N + col) = make_float2(v0, v1);
                }
            }
        }
    }
}

// ---------------- RoPE / relayout / cache copy (now also emit bf16) -----
__global__ __launch_bounds__(256) void rope_q_kernel(
    const float* __restrict__ in, const float* __restrict__ cosb,
    const float* __restrict__ sinb, __nv_bfloat16* __restrict__ Qh,
    __nv_bfloat16* __restrict__ Ql)
{
    int idx = blockIdx.x * 256 + threadIdx.x;
    int i = idx & 63;
    int h = (idx >> 6) & 15;
    int s = (idx >> 10) & 2047;
    int b = idx >> 21;
    int pos = PREV_LEN + s;
    float2 v = *(const float2*)(in + ((size_t)((b * S_LEN + s) * HEADS + h) * HD) + 2 * i);
    float c = cosb[pos * 64 + i], sn = sinb[pos * 64 + i];
    float x0 = (v.x * c - v.y * sn) * QK_SCALE;
    float x1 = (v.x * sn + v.y * c) * QK_SCALE;
    size_t off = ((size_t)((b * HEADS + h) * S_LEN + s) * HD) + 2 * i;
    split_store2(Qh, Ql, off, x0, x1);
}

__global__ __launch_bounds__(256) void rope_k_kernel(
    const float* __restrict__ in, const float* __restrict__ cosb,
    const float* __restrict__ sinb, float* __restrict__ out,
    __nv_bfloat16* __restrict__ Kh, __nv_bfloat16* __restrict__ Kl)
{
    int idx = blockIdx.x * 256 + threadIdx.x;
    int i = idx & 63;
    int h = (idx >> 6) & 15;
    int s = (idx >> 10) & 2047;
    int b = idx >> 21;
    int pos = PREV_LEN + s;
    float2 v = *(const float2*)(in + ((size_t)((b * S_LEN + s) * HEADS + h) * HD) + 2 * i);
    float c = cosb[pos * 64 + i], sn = sinb[pos * 64 + i];
    float x0 = v.x * c - v.y * sn;
    float x1 = v.x * sn + v.y * c;
    size_t off = ((size_t)((b * HEADS + h) * T_LEN + PREV_LEN + s) * HD) + 2 * i;
    *(float2*)(out + off) = make_float2(x0, x1);
    split_store2(Kh, Kl, off, x0, x1);
}

__global__ __launch_bounds__(256) void copy_v_kernel(
    const float* __restrict__ in, float* __restrict__ out,
    __nv_bfloat16* __restrict__ V16)
{
    int idx = blockIdx.x * 256 + threadIdx.x;
    int d4 = idx & 31;
    int h = (idx >> 5) & 15;
    int s = (idx >> 9) & 2047;
    int b = idx >> 20;
    float4 v = *(const float4*)(in + ((size_t)((b * S_LEN + s) * HEADS + h) * HD) + d4 * 4);
    size_t off = ((size_t)((b * HEADS + h) * T_LEN + PREV_LEN + s) * HD) + d4 * 4;
    *(float4*)(out + off) = v;
    __align__(8) __nv_bfloat16 bv[4];
    bv[0] = __float2bfloat16(v.x); bv[1] = __float2bfloat16(v.y);
    bv[2] = __float2bfloat16(v.z); bv[3] = __float2bfloat16(v.w);
    *(uint2*)(V16 + off) = *(const uint2*)bv;
}

__global__ __launch_bounds__(256) void copy_cache_k(
    const float* __restrict__ in, float* __restrict__ out,
    __nv_bfloat16* __restrict__ Kh, __nv_bfloat16* __restrict__ Kl)
{
    int idx = blockIdx.x * 256 + threadIdx.x;   // 2^20 f4
    int bh  = idx >> 15;
    int rem = idx & 32767;
    float4 v = ((const float4*)in)[idx];
    size_t off4 = (size_t)bh * (T_LEN * HD / 4) + rem;
    ((float4*)out)[off4] = v;
    size_t off = off4 * 4;
    split_store2(Kh, Kl, off,     v.x, v.y);
    split_store2(Kh, Kl, off + 2, v.z, v.w);
}

__global__ __launch_bounds__(256) void copy_cache_v(
    const float* __restrict__ in, float* __restrict__ out,
    __nv_bfloat16* __restrict__ V16)
{
    int idx = blockIdx.x * 256 + threadIdx.x;
    int bh  = idx >> 15;
    int rem = idx & 32767;
    float4 v = ((const float4*)in)[idx];
    size_t off4 = (size_t)bh * (T_LEN * HD / 4) + rem;
    ((float4*)out)[off4] = v;
    __align__(8) __nv_bfloat16 bv[4];
    bv[0] = __float2bfloat16(v.x); bv[1] = __float2bfloat16(v.y);
    bv[2] = __float2bfloat16(v.z); bv[3] = __float2bfloat16(v.w);
    *(uint2*)(V16 + off4 * 4) = *(const uint2*)bv;
}

// =====================================================================
// HMMA flash attention.
// CTA: 128 q-rows, 8 warps x 16 rows. Key tiles BN=64, 2-stage cp.async.
// S = Qh·Kh + Qh·Kl + Ql·Kh (3-pass split), P·V in plain bf16.
// smem: Qhi 32K | Qlo 32K | stage{0,1}: Khi 16K, Klo 16K, V 16K.
// =====================================================================
#define FBM 128
#define FBN 64
#define F_OFF_QH 0
#define F_OFF_QL 32768
#define F_OFF_ST 65536
#define F_STAGE  49152
#define F_SMEM   (F_OFF_ST + 2 * F_STAGE)   // 163840

__device__ __forceinline__ uint32_t swz256(int r, int g) {
    return (uint32_t)((r << 8) + (((g ^ (r & 7)) & 15) << 4));
}

__global__ void __launch_bounds__(256) flash_mma(
    const __nv_bfloat16* __restrict__ Qh, const __nv_bfloat16* __restrict__ Ql,
    const __nv_bfloat16* __restrict__ Kh, const __nv_bfloat16* __restrict__ Kl,
    const __nv_bfloat16* __restrict__ V16,
    __nv_bfloat16* __restrict__ Ohi, __nv_bfloat16* __restrict__ Olo)
{
    extern __shared__ char smraw[];
    const uint32_t sb = smem_u32(smraw);
    const int tid = threadIdx.x;
    const int wid = tid >> 5;
    const int lane = tid & 31;
    const int mtile = blockIdx.x;
    const int bh = blockIdx.y;
    const int m0 = mtile * FBM;
    const int jend = (PREV_LEN + m0 + FBM) / FBN;
    const int mask_start = (PREV_LEN + m0) / FBN;

    // ---- load Q hi/lo (group 0) ----
    {
        const size_t qo = ((size_t)bh * S_LEN + m0) * HD;
        for (int i = tid; i < 2048; i += 256) {
            int r = i >> 4, g = i & 15;
            uint32_t sw = swz256(r, g);
            cp_async16(sb + F_OFF_QH + sw, Qh + qo + (size_t)r * HD + g * 8);
            cp_async16(sb + F_OFF_QL + sw, Ql + qo + (size_t)r * HD + g * 8);
        }
        CP_COMMIT();
    }

    auto issue_kv = [&](int jt, int slot) {
        const uint32_t st = sb + F_OFF_ST + slot * F_STAGE;
        const size_t ko = ((size_t)bh * T_LEN + jt * FBN) * HD;
        for (int i = tid; i < 1024; i += 256) {
            int r = i >> 4, g = i & 15;
            uint32_t sw = swz256(r, g);
            size_t go = ko + (size_t)r * HD + g * 8;
            cp_async16(st + sw, Kh + go);
            cp_async16(st + 16384 + sw, Kl + go);
            cp_async16(st + 32768 + sw, V16 + go);
        }
    };
    issue_kv(0, 0); CP_COMMIT();
    issue_kv(1, 1); CP_COMMIT();

    float of[16][4];
    #pragma unroll
    for (int i = 0; i < 16; i++)
        #pragma unroll
        for (int j = 0; j < 4; j++) of[i][j] = 0.f;
    float mrow0 = -1e30f, mrow1 = -1e30f, lrow0 = 0.f, lrow1 = 0.f;

    const int arow = wid * 16 + (lane & 15);
    const int agr  = lane >> 4;

    for (int jt = 0; jt < jend; jt++) {
        CP_WAIT1();
        __syncthreads();
        const uint32_t st = sb + F_OFF_ST + (jt & 1) * F_STAGE;
        const int t0 = jt * FBN;

        // ---- S = 3-pass split Q.K ----
        float sf[8][4];
        #pragma unroll
        for (int i = 0; i < 8; i++)
            #pragma unroll
            for (int j = 0; j < 4; j++) sf[i][j] = 0.f;

        #pragma unroll
        for (int pass = 0; pass < 3; pass++) {
            const uint32_t qb = sb + (pass == 2 ? F_OFF_QL : F_OFF_QH);
            const uint32_t kb = st + (pass == 1 ? 16384 : 0);
            #pragma unroll
            for (int kt = 0; kt < 8; kt++) {
                uint32_t a[4];
                ldsm4(a, qb + swz256(arow, kt * 2 + agr));
                #pragma unroll
                for (int nb = 0; nb < 4; nb++) {
                    uint32_t b[4];
                    ldsm4(b, kb + swz256(nb * 16 + (lane & 15), kt * 2 + agr));
                    mma_bf16(sf[nb * 2 + 0], a, b[0], b[2]);
                    mma_bf16(sf[nb * 2 + 1], a, b[1], b[3]);
                }
            }
        }

        // ---- causal mask (last two tiles only) ----
        if (jt >= mask_start) {
            const int rb = m0 + wid * 16 + (lane >> 2);
            const int cb = t0 + (lane & 3) * 2;
            #pragma unroll
            for (int nt = 0; nt < 8; nt++) {
                const int c0 = cb + nt * 8;
                if (c0     > PREV_LEN + rb)     sf[nt][0] = -1e30f;
                if (c0 + 1 > PREV_LEN + rb)     sf[nt][1] = -1e30f;
                if (c0     > PREV_LEN + rb + 8) sf[nt][2] = -1e30f;
                if (c0 + 1 > PREV_LEN + rb + 8) sf[nt][3] = -1e30f;
            }
        }

        // ---- online softmax ----
        float mx0 = -1e30f, mx1 = -1e30f;
        #pragma unroll
        for (int nt = 0; nt < 8; nt++) {
            mx0 = fmaxf(mx0, fmaxf(sf[nt][0], sf[nt][1]));
            mx1 = fmaxf(mx1, fmaxf(sf[nt][2], sf[nt][3]));
        }
        mx0 = fmaxf(mx0, __shfl_xor_sync(0xFFFFFFFF, mx0, 1));
        mx0 = fmaxf(mx0, __shfl_xor_sync(0xFFFFFFFF, mx0, 2));
        mx1 = fmaxf(mx1, __shfl_xor_sync(0xFFFFFFFF, mx1, 1));
        mx1 = fmaxf(mx1, __shfl_xor_sync(0xFFFFFFFF, mx1, 2));
        const float nm0 = fmaxf(mrow0, mx0);
        const float nm1 = fmaxf(mrow1, mx1);
        const float al0 = __expf(mrow0 - nm0);
        const float al1 = __expf(mrow1 - nm1);
        mrow0 = nm0; mrow1 = nm1;

        float rs0 = 0.f, rs1 = 0.f;
        #pragma unroll
        for (int nt = 0; nt < 8; nt++) {
            sf[nt][0] = __expf(sf[nt][0] - nm0);
            sf[nt][1] = __expf(sf[nt][1] - nm0);
            sf[nt][2] = __expf(sf[nt][2] - nm1);
            sf[nt][3] = __expf(sf[nt][3] - nm1);
            rs0 += sf[nt][0] + sf[nt][1];
            rs1 += sf[nt][2] + sf[nt][3];
        }
        rs0 += __shfl_xor_sync(0xFFFFFFFF, rs0, 1);
        rs0 += __shfl_xor_sync(0xFFFFFFFF, rs0, 2);
        rs1 += __shfl_xor_sync(0xFFFFFFFF, rs1, 1);
        rs1 += __shfl_xor_sync(0xFFFFFFFF, rs1, 2);
        lrow0 = lrow0 * al0 + rs0;
        lrow1 = lrow1 * al1 + rs1;

        #pragma unroll
        for (int nt = 0; nt < 16; nt++) {
            of[nt][0] *= al0; of[nt][1] *= al0;
            of[nt][2] *= al1; of[nt][3] *= al1;
        }

        // ---- O += P.V ----
        #pragma unroll
        for (int kt = 0; kt < 4; kt++) {
            uint32_t a[4];
            a[0] = pack_bf16(sf[2 * kt][0],     sf[2 * kt][1]);
            a[1] = pack_bf16(sf[2 * kt][2],     sf[2 * kt][3]);
            a[2] = pack_bf16(sf[2 * kt + 1][0], sf[2 * kt + 1][1]);
            a[3] = pack_bf16(sf[2 * kt + 1][2], sf[2 * kt + 1][3]);
            const int vrow = kt * 16 + ((lane >> 3) & 1) * 8 + (lane & 7);
            #pragma unroll
            for (int nb = 0; nb < 8; nb++) {
                uint32_t b[4];
                ldsm4t(b, st + 32768 + swz256(vrow, nb * 2 + ((lane >> 4) & 1)));
                mma_bf16(of[nb * 2 + 0], a, b[0], b[1]);
                mma_bf16(of[nb * 2 + 1], a, b[2], b[3]);
            }
        }

        __syncthreads();
        if (jt + 2 < jend) issue_kv(jt + 2, jt & 1);
        CP_COMMIT();
    }

    // ---- normalize + hi/lo split write (b, s, dim) ----
    const float inv0 = 1.f / lrow0;
    const float inv1 = 1.f / lrow1;
    const int b = bh >> 4, h = bh & 15;
    const int r0 = m0 + wid * 16 + (lane >> 2);
    #pragma unroll
    for (int nt = 0; nt < 16; nt++) {
        const int gc = h * HD + nt * 8 + (lane & 3) * 2;
        split_store2(Ohi, Olo, (size_t)(b * S_LEN + r0) * DIM + gc,
                     of[nt][0] * inv0, of[nt][1] * inv0);
        split_store2(Ohi, Olo, (size_t)(b * S_LEN + r0 + 8) * DIM + gc,
                     of[nt][2] * inv1, of[nt][3] * inv1);
    }
}

// ---------------- launch ----------------
extern "C" void kernel_launch(void* const* d_in, const int* in_sizes, int n_in,
                              void* d_out, int out_size)
{
    const float* x          = (const float*)d_in[0];
    const float* k_cache    = (const float*)d_in[1];
    const float* v_cache    = (const float*)d_in[2];
    const float* attn_norm_w= (const float*)d_in[3];
    const float* ffn_norm_w = (const float*)d_in[4];
    const float* wq = (const float*)d_in[5];
    const float* bq = (const float*)d_in[6];
    const float* wk = (const float*)d_in[7];
    const float* bk = (const float*)d_in[8];
    const float* wv = (const float*)d_in[9];
    const float* bv = (const float*)d_in[10];
    const float* wo = (const float*)d_in[11];
    const float* bo = (const float*)d_in[12];
    const float* w_gate = (const float*)d_in[13];
    const float* b_gate = (const float*)d_in[14];
    const float* w_val  = (const float*)d_in[15];
    const float* b_val  = (const float*)d_in[16];
    const float* w_proj = (const float*)d_in[17];
    const float* b_proj = (const float*)d_in[18];
    const float* fcos   = (const float*)d_in[19];
    const float* fsin   = (const float*)d_in[20];

    float* out_x = (float*)d_out;
    float* out_k = out_x + OUT_X_ELEMS;
    float* out_v = out_k + OUT_KV_ELEMS;

    float *p_qt, *p_kt, *p_vt, *p_x1, *p_g;
    __nv_bfloat16 *p_hA_hi, *p_hA_lo, *p_h2_hi, *p_h2_lo, *p_o_hi, *p_o_lo, *p_gt_hi, *p_gt_lo;
    __nv_bfloat16 *p_q16h, *p_q16l, *p_k16h, *p_k16l, *p_v16;
    __nv_bfloat16 *p_wq_hi, *p_wq_lo, *p_wk_hi, *p_wk_lo, *p_wv_hi, *p_wv_lo, *p_wo_hi, *p_wo_lo;
    __nv_bfloat16 *p_wg_hi, *p_wg_lo, *p_wv2_hi, *p_wv2_lo, *p_wp_hi, *p_wp_lo;

    cudaGetSymbolAddress((void**)&p_qt, g_qt);
    cudaGetSymbolAddress((void**)&p_kt, g_kt);
    cudaGetSymbolAddress((void**)&p_vt, g_vt);
    cudaGetSymbolAddress((void**)&p_x1, g_x1);
    cudaGetSymbolAddress((void**)&p_g,  g_g);
    cudaGetSymbolAddress((void**)&p_hA_hi, g_hA_hi);
    cudaGetSymbolAddress((void**)&p_hA_lo, g_hA_lo);
    cudaGetSymbolAddress((void**)&p_h2_hi, g_h2_hi);
    cudaGetSymbolAddress((void**)&p_h2_lo, g_h2_lo);
    cudaGetSymbolAddress((void**)&p_o_hi,  g_o_hi);
    cudaGetSymbolAddress((void**)&p_o_lo,  g_o_lo);
    cudaGetSymbolAddress((void**)&p_gt_hi, g_gt_hi);
    cudaGetSymbolAddress((void**)&p_gt_lo, g_gt_lo);
    cudaGetSymbolAddress((void**)&p_q16h, g_q16h);
    cudaGetSymbolAddress((void**)&p_q16l, g_q16l);
    cudaGetSymbolAddress((void**)&p_k16h, g_k16h);
    cudaGetSymbolAddress((void**)&p_k16l, g_k16l);
    cudaGetSymbolAddress((void**)&p_v16,  g_v16);
    cudaGetSymbolAddress((void**)&p_wq_hi, g_wq_hi);
    cudaGetSymbolAddress((void**)&p_wq_lo, g_wq_lo);
    cudaGetSymbolAddress((void**)&p_wk_hi, g_wk_hi);
    cudaGetSymbolAddress((void**)&p_wk_lo, g_wk_lo);
    cudaGetSymbolAddress((void**)&p_wv_hi, g_wv_hi);
    cudaGetSymbolAddress((void**)&p_wv_lo, g_wv_lo);
    cudaGetSymbolAddress((void**)&p_wo_hi, g_wo_hi);
    cudaGetSymbolAddress((void**)&p_wo_lo, g_wo_lo);
    cudaGetSymbolAddress((void**)&p_wg_hi, g_wg_hi);
    cudaGetSymbolAddress((void**)&p_wg_lo, g_wg_lo);
    cudaGetSymbolAddress((void**)&p_wv2_hi, g_wv2_hi);
    cudaGetSymbolAddress((void**)&p_wv2_lo, g_wv2_lo);
    cudaGetSymbolAddress((void**)&p_wp_hi, g_wp_hi);
    cudaGetSymbolAddress((void**)&p_wp_lo, g_wp_lo);

    cudaFuncSetAttribute(gemm_mma<0>, cudaFuncAttributeMaxDynamicSharedMemorySize, GM_SMEM);
    cudaFuncSetAttribute(gemm_mma<1>, cudaFuncAttributeMaxDynamicSharedMemorySize, GM_SMEM);
    cudaFuncSetAttribute(gemm_mma<2>, cudaFuncAttributeMaxDynamicSharedMemorySize, GM_SMEM);
    cudaFuncSetAttribute(flash_mma, cudaFuncAttributeMaxDynamicSharedMemorySize, F_SMEM);

    // ---- weight conversion + transpose ----
    weight_conv_t<<<dim3(64, 64), 256>>>(wq, p_wq_hi, p_wq_lo, DIM, DIM);
    weight_conv_t<<<dim3(64, 64), 256>>>(wk, p_wk_hi, p_wk_lo, DIM, DIM);
    weight_conv_t<<<dim3(64, 64), 256>>>(wv, p_wv_hi, p_wv_lo, DIM, DIM);
    weight_conv_t<<<dim3(64, 64), 256>>>(wo, p_wo_hi, p_wo_lo, DIM, DIM);
    weight_conv_t<<<dim3(64, 256), 256>>>(w_gate, p_wg_hi,  p_wg_lo,  FF_DIM, DIM);
    weight_conv_t<<<dim3(64, 256), 256>>>(w_val,  p_wv2_hi, p_wv2_lo, FF_DIM, DIM);
    weight_conv_t<<<dim3(256, 64), 256>>>(w_proj, p_wp_hi,  p_wp_lo,  DIM, FF_DIM);

    // ---- attention block ----
    rmsnorm_split<<<ROWS, 256>>>(x, attn_norm_w, p_hA_hi, p_hA_lo);
    gemm_mma<0><<<dim3(16, 32), 256, GM_SMEM>>>(
        p_hA_hi, p_hA_lo, p_wq_hi, p_wq_lo, bq, nullptr, p_qt, nullptr, nullptr, ROWS, DIM, DIM);
    gemm_mma<0><<<dim3(16, 32), 256, GM_SMEM>>>(
        p_hA_hi, p_hA_lo, p_wk_hi, p_wk_lo, bk, nullptr, p_kt, nullptr, nullptr, ROWS, DIM, DIM);
    gemm_mma<0><<<dim3(16, 32), 256, GM_SMEM>>>(
        p_hA_hi, p_hA_lo, p_wv_hi, p_wv_lo, bv, nullptr, p_vt, nullptr, nullptr, ROWS, DIM, DIM);

    rope_q_kernel<<<16384, 256>>>(p_qt, fcos, fsin, p_q16h, p_q16l);
    rope_k_kernel<<<16384, 256>>>(p_kt, fcos, fsin, out_k, p_k16h, p_k16l);
    copy_v_kernel<<<8192, 256>>>(p_vt, out_v, p_v16);
    copy_cache_k<<<4096, 256>>>(k_cache, out_k, p_k16h, p_k16l);
    copy_cache_v<<<4096, 256>>>(v_cache, out_v, p_v16);

    flash_mma<<<dim3(S_LEN / FBM, BATCH * HEADS), 256, F_SMEM>>>(
        p_q16h, p_q16l, p_k16h, p_k16l, p_v16, p_o_hi, p_o_lo);

    gemm_mma<1><<<dim3(16, 32), 256, GM_SMEM>>>(
        p_o_hi, p_o_lo, p_wo_hi, p_wo_lo, bo, x, p_x1, nullptr, nullptr, ROWS, DIM, DIM);

    // ---- ffn block ----
    rmsnorm_split<<<ROWS, 256>>>(p_x1, ffn_norm_w, p_h2_hi, p_h2_lo);
    gemm_mma<0><<<dim3(64, 32), 256, GM_SMEM>>>(
        p_h2_hi, p_h2_lo, p_wg_hi, p_wg_lo, b_gate, nullptr, p_g, nullptr, nullptr, ROWS, FF_DIM, DIM);
    gemm_mma<2><<<dim3(64, 32), 256, GM_SMEM>>>(
        p_h2_hi, p_h2_lo, p_wv2_hi, p_wv2_lo, b_val, p_g, nullptr, p_gt_hi, p_gt_lo, ROWS, FF_DIM, DIM);
    gemm_mma<1><<<dim3(16, 32), 256, GM_SMEM>>>(
        p_gt_hi, p_gt_lo, p_wp_hi, p_wp_lo, b_proj, p_x1, out_x, nullptr, nullptr, ROWS, DIM, FF_DIM);
}

// round 5
// speedup vs baseline: 4.2069x; 1.0877x over previous
#include <cuda_runtime.h>
#include <cuda_bf16.h>
#include <cstdint>

// ---------------- problem constants ----------------
#define BATCH 2
#define S_LEN 2048
#define PREV_LEN 1024
#define T_LEN 3072
#define DIM 2048
#define HEADS 16
#define HD 128
#define FF_DIM 8192
#define ROWS (BATCH * S_LEN)  // 4096
#define QK_SCALE 0.08838834764831845f

#define OUT_X_ELEMS  (BATCH * S_LEN * DIM)
#define OUT_KV_ELEMS (BATCH * HEADS * T_LEN * HD)

// ================= PTX helpers (portable sm_80+) ====
__device__ __forceinline__ uint32_t smem_u32(const void* p) {
    uint32_t a;
    asm("{ .reg .u64 t; cvta.to.shared.u64 t, %1; cvt.u32.u64 %0, t; }" : "=r"(a) : "l"(p));
    return a;
}
__device__ __forceinline__ void cp_async16(uint32_t smem, const void* g) {
    asm volatile("cp.async.cg.shared.global [%0], [%1], 16;" :: "r"(smem), "l"(g) : "memory");
}
#define CP_COMMIT() asm volatile("cp.async.commit_group;" ::: "memory")
#define CP_WAIT2()  asm volatile("cp.async.wait_group 2;" ::: "memory")
#define CP_WAIT1()  asm volatile("cp.async.wait_group 1;" ::: "memory")

__device__ __forceinline__ void ldsm4(uint32_t* r, uint32_t addr) {
    asm volatile("ldmatrix.sync.aligned.m8n8.x4.shared.b16 {%0,%1,%2,%3}, [%4];"
        : "=r"(r[0]), "=r"(r[1]), "=r"(r[2]), "=r"(r[3]) : "r"(addr));
}
__device__ __forceinline__ void ldsm4t(uint32_t* r, uint32_t addr) {
    asm volatile("ldmatrix.sync.aligned.m8n8.x4.trans.shared.b16 {%0,%1,%2,%3}, [%4];"
        : "=r"(r[0]), "=r"(r[1]), "=r"(r[2]), "=r"(r[3]) : "r"(addr));
}
__device__ __forceinline__ void mma_bf16(float* c, const uint32_t* a, uint32_t b0, uint32_t b1) {
    asm volatile(
        "mma.sync.aligned.m16n8k16.row.col.f32.bf16.bf16.f32 "
        "{%0,%1,%2,%3}, {%4,%5,%6,%7}, {%8,%9}, {%0,%1,%2,%3};"
        : "+f"(c[0]), "+f"(c[1]), "+f"(c[2]), "+f"(c[3])
        : "r"(a[0]), "r"(a[1]), "r"(a[2]), "r"(a[3]), "r"(b0), "r"(b1));
}
__device__ __forceinline__ uint32_t pack_bf16(float a, float b) {
    __nv_bfloat162 t = __floats2bfloat162_rn(a, b);
    return *(uint32_t*)&t;
}
__device__ __forceinline__ void split_store2(
    __nv_bfloat16* Hi, __nv_bfloat16* Lo, size_t off, float a, float b)
{
    __nv_bfloat16 ha = __float2bfloat16(a), hb = __float2bfloat16(b);
    __nv_bfloat162 hh; hh.x = ha; hh.y = hb;
    __nv_bfloat162 ll;
    ll.x = __float2bfloat16(a - __bfloat162float(ha));
    ll.y = __float2bfloat16(b - __bfloat162float(hb));
    *(__nv_bfloat162*)(Hi + off) = hh;
    *(__nv_bfloat162*)(Lo + off) = ll;
}

// ---------------- scratch (device globals) --------
__device__ float g_qt [ROWS * DIM];
__device__ float g_kt [ROWS * DIM];
__device__ float g_vt [ROWS * DIM];
__device__ float g_x1 [ROWS * DIM];
__device__ float g_g  [ROWS * FF_DIM];
// bf16 hi/lo row-major activations
__device__ __nv_bfloat16 g_hA_hi [ROWS * DIM];
__device__ __nv_bfloat16 g_hA_lo [ROWS * DIM];
__device__ __nv_bfloat16 g_h2_hi [ROWS * DIM];
__device__ __nv_bfloat16 g_h2_lo [ROWS * DIM];
__device__ __nv_bfloat16 g_o_hi  [ROWS * DIM];
__device__ __nv_bfloat16 g_o_lo  [ROWS * DIM];
__device__ __nv_bfloat16 g_gt_hi [ROWS * FF_DIM];
__device__ __nv_bfloat16 g_gt_lo [ROWS * FF_DIM];
// bf16 attention operands (b,h,s/t,d)
__device__ __nv_bfloat16 g_q16h [ROWS * DIM];
__device__ __nv_bfloat16 g_q16l [ROWS * DIM];
__device__ __nv_bfloat16 g_k16h [OUT_KV_ELEMS];
__device__ __nv_bfloat16 g_k16l [OUT_KV_ELEMS];
__device__ __nv_bfloat16 g_v16  [OUT_KV_ELEMS];
// bf16 hi/lo transposed weights [N][K]
__device__ __nv_bfloat16 g_wq_hi [DIM * DIM];
__device__ __nv_bfloat16 g_wq_lo [DIM * DIM];
__device__ __nv_bfloat16 g_wk_hi [DIM * DIM];
__device__ __nv_bfloat16 g_wk_lo [DIM * DIM];
__device__ __nv_bfloat16 g_wv_hi [DIM * DIM];
__device__ __nv_bfloat16 g_wv_lo [DIM * DIM];
__device__ __nv_bfloat16 g_wo_hi [DIM * DIM];
__device__ __nv_bfloat16 g_wo_lo [DIM * DIM];
__device__ __nv_bfloat16 g_wg_hi [DIM * FF_DIM];
__device__ __nv_bfloat16 g_wg_lo [DIM * FF_DIM];
__device__ __nv_bfloat16 g_wv2_hi[DIM * FF_DIM];
__device__ __nv_bfloat16 g_wv2_lo[DIM * FF_DIM];
__device__ __nv_bfloat16 g_wp_hi [FF_DIM * DIM];
__device__ __nv_bfloat16 g_wp_lo [FF_DIM * DIM];

// =====================================================================
// Weight converter + transpose: W[K][N] fp32 -> Wt[N][K] bf16 hi/lo.
// =====================================================================
__global__ __launch_bounds__(256) void weight_conv_t(
    const float* __restrict__ W, __nv_bfloat16* __restrict__ Thi,
    __nv_bfloat16* __restrict__ Tlo, int N, int K)
{
    __shared__ float tile[32][33];
    const int k0 = blockIdx.x * 32, n0 = blockIdx.y * 32;
    const int tx = threadIdx.x & 31, ty = threadIdx.x >> 5;
    #pragma unroll
    for (int i = 0; i < 4; i++) {
        int k = ty + i * 8;
        tile[k][tx] = W[(size_t)(k0 + k) * N + n0 + tx];
    }
    __syncthreads();
    #pragma unroll
    for (int i = 0; i < 4; i++) {
        int n = ty + i * 8;
        float v = tile[tx][n];
        __nv_bfloat16 h = __float2bfloat16(v);
        Thi[(size_t)(n0 + n) * K + k0 + tx] = h;
        Tlo[(size_t)(n0 + n) * K + k0 + tx] = __float2bfloat16(v - __bfloat162float(h));
    }
}

// =====================================================================
// rmsnorm -> hi/lo bf16 row-major
// =====================================================================
__global__ __launch_bounds__(256) void rmsnorm_split(
    const float* __restrict__ x, const float* __restrict__ w,
    __nv_bfloat16* __restrict__ Ohi, __nv_bfloat16* __restrict__ Olo)
{
    __shared__ float red[256];
    const int tid = threadIdx.x;
    const int m = blockIdx.x;
    const float* xp = x + (size_t)m * DIM + tid * 8;
    float4 a = *(const float4*)xp;
    float4 b = *(const float4*)(xp + 4);
    float s = a.x*a.x + a.y*a.y + a.z*a.z + a.w*a.w
            + b.x*b.x + b.y*b.y + b.z*b.z + b.w*b.w;
    red[tid] = s;
    __syncthreads();
    #pragma unroll
    for (int off = 128; off > 0; off >>= 1) {
        if (tid < off) red[tid] += red[tid + off];
        __syncthreads();
    }
    float scale = rsqrtf(red[0] * (1.0f / DIM) + 1e-6f);
    const float* wp = w + tid * 8;
    float4 wa = *(const float4*)wp;
    float4 wb = *(const float4*)(wp + 4);
    float y[8];
    y[0] = a.x*scale*wa.x; y[1] = a.y*scale*wa.y; y[2] = a.z*scale*wa.z; y[3] = a.w*scale*wa.w;
    y[4] = b.x*scale*wb.x; y[5] = b.y*scale*wb.y; y[6] = b.z*scale*wb.z; y[7] = b.w*scale*wb.w;
    __align__(16) __nv_bfloat16 hv[8], lv[8];
    #pragma unroll
    for (int j = 0; j < 8; j++) {
        __nv_bfloat16 h16 = __float2bfloat16(y[j]);
        hv[j] = h16;
        lv[j] = __float2bfloat16(y[j] - __bfloat162float(h16));
    }
    *(uint4*)(Ohi + (size_t)m * DIM + tid * 8) = *(const uint4*)hv;
    *(uint4*)(Olo + (size_t)m * DIM + tid * 8) = *(const uint4*)lv;
}

// =====================================================================
// HMMA split-bf16 GEMM v2. CTA tile 128(M) x 256(N), warp tile 64x64,
// 8 warps (2m x 4n), K-chunk 32, 4-stage cp.async pipeline.
// A row-major [M][K] hi/lo bf16; B transposed [N][K] hi/lo bf16 (TN).
// MODE 0: C = A@B + bias            (fp32 out)
// MODE 1: C = A@B + bias + extra    (fp32 out)
// MODE 2: Chi/Clo = split(silu(extra) * (A@B + bias))  (bf16 out)
// =====================================================================
#define GM_STAGES 4
#define GM_STAGE_BYTES 49152
#define GM_SMEM (GM_STAGES * GM_STAGE_BYTES)   // 196608
#define OFF_AH 0
#define OFF_AL 8192
#define OFF_BH 16384
#define OFF_BL 32768

__device__ __forceinline__ uint32_t swz(int r, int g) {
    return (uint32_t)(r * 64 + ((g ^ ((r >> 1) & 3)) << 4));
}

template<int MODE>
__global__ void __launch_bounds__(256, 1) gemm_mma(
    const __nv_bfloat16* __restrict__ Ahi, const __nv_bfloat16* __restrict__ Alo,
    const __nv_bfloat16* __restrict__ Bhi, const __nv_bfloat16* __restrict__ Blo,
    const float* __restrict__ bias, const float* __restrict__ extra,
    float* __restrict__ C, __nv_bfloat16* __restrict__ Chi, __nv_bfloat16* __restrict__ Clo,
    int M, int N, int K)
{
    extern __shared__ char smraw[];
    const uint32_t sb = smem_u32(smraw);
    const int tid = threadIdx.x;
    const int wid = tid >> 5;
    const int lane = tid & 31;
    const int wm = wid & 1;        // 2 m-groups of 64 rows
    const int wn = wid >> 1;       // 4 n-groups of 64 cols
    const int ntile = blockIdx.x;
    const int mtile = blockIdx.y;
    const int m0 = mtile * 128;
    const int n0 = ntile * 256;
    const int nk = K >> 5;

    const int lr = tid >> 2;       // 0..63
    const int lg = tid & 3;        // 0..3

    float acc[4][8][4];
    #pragma unroll
    for (int a = 0; a < 4; a++)
        #pragma unroll
        for (int b = 0; b < 8; b++)
            #pragma unroll
            for (int c = 0; c < 4; c++) acc[a][b][c] = 0.f;

    auto issue_stage = [&](int kc, int slot) {
        const uint32_t st = sb + slot * GM_STAGE_BYTES;
        const int kelem = kc * 32 + lg * 8;
        #pragma unroll
        for (int i = 0; i < 2; i++) {
            const int r = lr + i * 64;
            const uint32_t sw = swz(r, lg);
            cp_async16(st + OFF_AH + sw, Ahi + (size_t)(m0 + r) * K + kelem);
            cp_async16(st + OFF_AL + sw, Alo + (size_t)(m0 + r) * K + kelem);
        }
        #pragma unroll
        for (int i = 0; i < 4; i++) {
            const int r = lr + i * 64;
            const uint32_t sw = swz(r, lg);
            cp_async16(st + OFF_BH + sw, Bhi + (size_t)(n0 + r) * K + kelem);
            cp_async16(st + OFF_BL + sw, Blo + (size_t)(n0 + r) * K + kelem);
        }
    };

    issue_stage(0, 0); CP_COMMIT();
    issue_stage(1, 1); CP_COMMIT();
    issue_stage(2, 2); CP_COMMIT();

    for (int kc = 0; kc < nk; kc++) {
        CP_WAIT2();
        __syncthreads();
        if (kc + 3 < nk) issue_stage(kc + 3, (kc + 3) & 3);
        CP_COMMIT();

        const uint32_t st = sb + (kc & 3) * GM_STAGE_BYTES;
        #pragma unroll
        for (int h = 0; h < 2; h++) {
            uint32_t ah[4][4], al[4][4];
            #pragma unroll
            for (int mi = 0; mi < 4; mi++) {
                const int r = wm * 64 + mi * 16 + (lane & 15);
                const uint32_t sw = swz(r, h * 2 + (lane >> 4));
                ldsm4(ah[mi], st + OFF_AH + sw);
                ldsm4(al[mi], st + OFF_AL + sw);
            }
            #pragma unroll
            for (int ng = 0; ng < 4; ng++) {
                uint32_t bh[4], bl[4];
                const int r = wn * 64 + ng * 16 + (lane & 15);
                const uint32_t sw = swz(r, h * 2 + (lane >> 4));
                ldsm4(bh, st + OFF_BH + sw);
                ldsm4(bl, st + OFF_BL + sw);
                #pragma unroll
                for (int mi = 0; mi < 4; mi++) {
                    mma_bf16(acc[mi][ng * 2 + 0], ah[mi], bh[0], bh[2]);
                    mma_bf16(acc[mi][ng * 2 + 1], ah[mi], bh[1], bh[3]);
                    mma_bf16(acc[mi][ng * 2 + 0], ah[mi], bl[0], bl[2]);
                    mma_bf16(acc[mi][ng * 2 + 1], ah[mi], bl[1], bl[3]);
                    mma_bf16(acc[mi][ng * 2 + 0], al[mi], bh[0], bh[2]);
                    mma_bf16(acc[mi][ng * 2 + 1], al[mi], bh[1], bh[3]);
                }
            }
        }
        __syncthreads();
    }

    // ---------------- epilogue ----------------
    const int mb = m0 + wm * 64;
    const int nb = n0 + wn * 64;
    #pragma unroll
    for (int mi = 0; mi < 4; mi++) {
        #pragma unroll
        for (int j = 0; j < 8; j++) {
            const int row = mb + mi * 16 + (lane >> 2);
            const int col = nb + j * 8 + (lane & 3) * 2;
            const float b0 = bias[col], b1 = bias[col + 1];
            #pragma unroll
            for (int half = 0; half < 2; half++) {
                const int rr = row + half * 8;
                float v0 = acc[mi][j][half * 2 + 0] + b0;
                float v1 = acc[mi][j][half * 2 + 1] + b1;
                if (MODE == 1) {
                    const float* ep = extra + (size_t)rr * N + col;
                    v0 += ep[0]; v1 += ep[1];
                }
                if (MODE == 2) {
                    const float* ep = extra + (size_t)rr * N + col;
                    float g0 = ep[0], g1 = ep[1];
                    v0 *= g0 / (1.f + __expf(-g0));
                    v1 *= g1 / (1.f + __expf(-g1));
                    split_store2(Chi, Clo, (size_t)rr * N + col, v0, v1);
                } else {
                    *(float2*)(C + (size_t)rr * N + col) = make_float2(v0, v1);
                }
            }
        }
    }
}

// ---------------- RoPE / relayout / cache copy ----------------
__global__ __launch_bounds__(256) void rope_q_kernel(
    const float* __restrict__ in, const float* __restrict__ cosb,
    const float* __restrict__ sinb, __nv_bfloat16* __restrict__ Qh,
    __nv_bfloat16* __restrict__ Ql)
{
    int idx = blockIdx.x * 256 + threadIdx.x;
    int i = idx & 63;
    int h = (idx >> 6) & 15;
    int s = (idx >> 10) & 2047;
    int b = idx >> 21;
    int pos = PREV_LEN + s;
    float2 v = *(const float2*)(in + ((size_t)((b * S_LEN + s) * HEADS + h) * HD) + 2 * i);
    float c = cosb[pos * 64 + i], sn = sinb[pos * 64 + i];
    float x0 = (v.x * c - v.y * sn) * QK_SCALE;
    float x1 = (v.x * sn + v.y * c) * QK_SCALE;
    size_t off = ((size_t)((b * HEADS + h) * S_LEN + s) * HD) + 2 * i;
    split_store2(Qh, Ql, off, x0, x1);
}

__global__ __launch_bounds__(256) void rope_k_kernel(
    const float* __restrict__ in, const float* __restrict__ cosb,
    const float* __restrict__ sinb, float* __restrict__ out,
    __nv_bfloat16* __restrict__ Kh, __nv_bfloat16* __restrict__ Kl)
{
    int idx = blockIdx.x * 256 + threadIdx.x;
    int i = idx & 63;
    int h = (idx >> 6) & 15;
    int s = (idx >> 10) & 2047;
    int b = idx >> 21;
    int pos = PREV_LEN + s;
    float2 v = *(const float2*)(in + ((size_t)((b * S_LEN + s) * HEADS + h) * HD) + 2 * i);
    float c = cosb[pos * 64 + i], sn = sinb[pos * 64 + i];
    float x0 = v.x * c - v.y * sn;
    float x1 = v.x * sn + v.y * c;
    size_t off = ((size_t)((b * HEADS + h) * T_LEN + PREV_LEN + s) * HD) + 2 * i;
    *(float2*)(out + off) = make_float2(x0, x1);
    split_store2(Kh, Kl, off, x0, x1);
}

__global__ __launch_bounds__(256) void copy_v_kernel(
    const float* __restrict__ in, float* __restrict__ out,
    __nv_bfloat16* __restrict__ V16)
{
    int idx = blockIdx.x * 256 + threadIdx.x;
    int d4 = idx & 31;
    int h = (idx >> 5) & 15;
    int s = (idx >> 9) & 2047;
    int b = idx >> 20;
    float4 v = *(const float4*)(in + ((size_t)((b * S_LEN + s) * HEADS + h) * HD) + d4 * 4);
    size_t off = ((size_t)((b * HEADS + h) * T_LEN + PREV_LEN + s) * HD) + d4 * 4;
    *(float4*)(out + off) = v;
    __align__(8) __nv_bfloat16 bv[4];
    bv[0] = __float2bfloat16(v.x); bv[1] = __float2bfloat16(v.y);
    bv[2] = __float2bfloat16(v.z); bv[3] = __float2bfloat16(v.w);
    *(uint2*)(V16 + off) = *(const uint2*)bv;
}

__global__ __launch_bounds__(256) void copy_cache_k(
    const float* __restrict__ in, float* __restrict__ out,
    __nv_bfloat16* __restrict__ Kh, __nv_bfloat16* __restrict__ Kl)
{
    int idx = blockIdx.x * 256 + threadIdx.x;   // 2^20 f4
    int bh  = idx >> 15;
    int rem = idx & 32767;
    float4 v = ((const float4*)in)[idx];
    size_t off4 = (size_t)bh * (T_LEN * HD / 4) + rem;
    ((float4*)out)[off4] = v;
    size_t off = off4 * 4;
    split_store2(Kh, Kl, off,     v.x, v.y);
    split_store2(Kh, Kl, off + 2, v.z, v.w);
}

__global__ __launch_bounds__(256) void copy_cache_v(
    const float* __restrict__ in, float* __restrict__ out,
    __nv_bfloat16* __restrict__ V16)
{
    int idx = blockIdx.x * 256 + threadIdx.x;
    int bh  = idx >> 15;
    int rem = idx & 32767;
    float4 v = ((const float4*)in)[idx];
    size_t off4 = (size_t)bh * (T_LEN * HD / 4) + rem;
    ((float4*)out)[off4] = v;
    __align__(8) __nv_bfloat16 bv[4];
    bv[0] = __float2bfloat16(v.x); bv[1] = __float2bfloat16(v.y);
    bv[2] = __float2bfloat16(v.z); bv[3] = __float2bfloat16(v.w);
    *(uint2*)(V16 + off4 * 4) = *(const uint2*)bv;
}

// =====================================================================
// HMMA flash attention (unchanged from passing round).
// =====================================================================
#define FBM 128
#define FBN 64
#define F_OFF_QH 0
#define F_OFF_QL 32768
#define F_OFF_ST 65536
#define F_STAGE  49152
#define F_SMEM   (F_OFF_ST + 2 * F_STAGE)   // 163840

__device__ __forceinline__ uint32_t swz256(int r, int g) {
    return (uint32_t)((r << 8) + (((g ^ (r & 7)) & 15) << 4));
}

__global__ void __launch_bounds__(256) flash_mma(
    const __nv_bfloat16* __restrict__ Qh, const __nv_bfloat16* __restrict__ Ql,
    const __nv_bfloat16* __restrict__ Kh, const __nv_bfloat16* __restrict__ Kl,
    const __nv_bfloat16* __restrict__ V16,
    __nv_bfloat16* __restrict__ Ohi, __nv_bfloat16* __restrict__ Olo)
{
    extern __shared__ char smraw[];
    const uint32_t sb = smem_u32(smraw);
    const int tid = threadIdx.x;
    const int wid = tid >> 5;
    const int lane = tid & 31;
    const int mtile = blockIdx.x;
    const int bh = blockIdx.y;
    const int m0 = mtile * FBM;
    const int jend = (PREV_LEN + m0 + FBM) / FBN;
    const int mask_start = (PREV_LEN + m0) / FBN;

    {
        const size_t qo = ((size_t)bh * S_LEN + m0) * HD;
        for (int i = tid; i < 2048; i += 256) {
            int r = i >> 4, g = i & 15;
            uint32_t sw = swz256(r, g);
            cp_async16(sb + F_OFF_QH + sw, Qh + qo + (size_t)r * HD + g * 8);
            cp_async16(sb + F_OFF_QL + sw, Ql + qo + (size_t)r * HD + g * 8);
        }
        CP_COMMIT();
    }

    auto issue_kv = [&](int jt, int slot) {
        const uint32_t st = sb + F_OFF_ST + slot * F_STAGE;
        const size_t ko = ((size_t)bh * T_LEN + jt * FBN) * HD;
        for (int i = tid; i < 1024; i += 256) {
            int r = i >> 4, g = i & 15;
            uint32_t sw = swz256(r, g);
            size_t go = ko + (size_t)r * HD + g * 8;
            cp_async16(st + sw, Kh + go);
            cp_async16(st + 16384 + sw, Kl + go);
            cp_async16(st + 32768 + sw, V16 + go);
        }
    };
    issue_kv(0, 0); CP_COMMIT();
    issue_kv(1, 1); CP_COMMIT();

    float of[16][4];
    #pragma unroll
    for (int i = 0; i < 16; i++)
        #pragma unroll
        for (int j = 0; j < 4; j++) of[i][j] = 0.f;
    float mrow0 = -1e30f, mrow1 = -1e30f, lrow0 = 0.f, lrow1 = 0.f;

    const int arow = wid * 16 + (lane & 15);
    const int agr  = lane >> 4;

    for (int jt = 0; jt < jend; jt++) {
        CP_WAIT1();
        __syncthreads();
        const uint32_t st = sb + F_OFF_ST + (jt & 1) * F_STAGE;
        const int t0 = jt * FBN;

        float sf[8][4];
        #pragma unroll
        for (int i = 0; i < 8; i++)
            #pragma unroll
            for (int j = 0; j < 4; j++) sf[i][j] = 0.f;

        #pragma unroll
        for (int pass = 0; pass < 3; pass++) {
            const uint32_t qb = sb + (pass == 2 ? F_OFF_QL : F_OFF_QH);
            const uint32_t kb = st + (pass == 1 ? 16384 : 0);
            #pragma unroll
            for (int kt = 0; kt < 8; kt++) {
                uint32_t a[4];
                ldsm4(a, qb + swz256(arow, kt * 2 + agr));
                #pragma unroll
                for (int nb = 0; nb < 4; nb++) {
                    uint32_t b[4];
                    ldsm4(b, kb + swz256(nb * 16 + (lane & 15), kt * 2 + agr));
                    mma_bf16(sf[nb * 2 + 0], a, b[0], b[2]);
                    mma_bf16(sf[nb * 2 + 1], a, b[1], b[3]);
                }
            }
        }

        if (jt >= mask_start) {
            const int rb = m0 + wid * 16 + (lane >> 2);
            const int cb = t0 + (lane & 3) * 2;
            #pragma unroll
            for (int nt = 0; nt < 8; nt++) {
                const int c0 = cb + nt * 8;
                if (c0     > PREV_LEN + rb)     sf[nt][0] = -1e30f;
                if (c0 + 1 > PREV_LEN + rb)     sf[nt][1] = -1e30f;
                if (c0     > PREV_LEN + rb + 8) sf[nt][2] = -1e30f;
                if (c0 + 1 > PREV_LEN + rb + 8) sf[nt][3] = -1e30f;
            }
        }

        float mx0 = -1e30f, mx1 = -1e30f;
        #pragma unroll
        for (int nt = 0; nt < 8; nt++) {
            mx0 = fmaxf(mx0, fmaxf(sf[nt][0], sf[nt][1]));
            mx1 = fmaxf(mx1, fmaxf(sf[nt][2], sf[nt][3]));
        }
        mx0 = fmaxf(mx0, __shfl_xor_sync(0xFFFFFFFF, mx0, 1));
        mx0 = fmaxf(mx0, __shfl_xor_sync(0xFFFFFFFF, mx0, 2));
        mx1 = fmaxf(mx1, __shfl_xor_sync(0xFFFFFFFF, mx1, 1));
        mx1 = fmaxf(mx1, __shfl_xor_sync(0xFFFFFFFF, mx1, 2));
        const float nm0 = fmaxf(mrow0, mx0);
        const float nm1 = fmaxf(mrow1, mx1);
        const float al0 = __expf(mrow0 - nm0);
        const float al1 = __expf(mrow1 - nm1);
        mrow0 = nm0; mrow1 = nm1;

        float rs0 = 0.f, rs1 = 0.f;
        #pragma unroll
        for (int nt = 0; nt < 8; nt++) {
            sf[nt][0] = __expf(sf[nt][0] - nm0);
            sf[nt][1] = __expf(sf[nt][1] - nm0);
            sf[nt][2] = __expf(sf[nt][2] - nm1);
            sf[nt][3] = __expf(sf[nt][3] - nm1);
            rs0 += sf[nt][0] + sf[nt][1];
            rs1 += sf[nt][2] + sf[nt][3];
        }
        rs0 += __shfl_xor_sync(0xFFFFFFFF, rs0, 1);
        rs0 += __shfl_xor_sync(0xFFFFFFFF, rs0, 2);
        rs1 += __shfl_xor_sync(0xFFFFFFFF, rs1, 1);
        rs1 += __shfl_xor_sync(0xFFFFFFFF, rs1, 2);
        lrow0 = lrow0 * al0 + rs0;
        lrow1 = lrow1 * al1 + rs1;

        #pragma unroll
        for (int nt = 0; nt < 16; nt++) {
            of[nt][0] *= al0; of[nt][1] *= al0;
            of[nt][2] *= al1; of[nt][3] *= al1;
        }

        #pragma unroll
        for (int kt = 0; kt < 4; kt++) {
            uint32_t a[4];
            a[0] = pack_bf16(sf[2 * kt][0],     sf[2 * kt][1]);
            a[1] = pack_bf16(sf[2 * kt][2],     sf[2 * kt][3]);
            a[2] = pack_bf16(sf[2 * kt + 1][0], sf[2 * kt + 1][1]);
            a[3] = pack_bf16(sf[2 * kt + 1][2], sf[2 * kt + 1][3]);
            const int vrow = kt * 16 + ((lane >> 3) & 1) * 8 + (lane & 7);
            #pragma unroll
            for (int nb = 0; nb < 8; nb++) {
                uint32_t b[4];
                ldsm4t(b, st + 32768 + swz256(vrow, nb * 2 + ((lane >> 4) & 1)));
                mma_bf16(of[nb * 2 + 0], a, b[0], b[1]);
                mma_bf16(of[nb * 2 + 1], a, b[2], b[3]);
            }
        }

        __syncthreads();
        if (jt + 2 < jend) issue_kv(jt + 2, jt & 1);
        CP_COMMIT();
    }

    const float inv0 = 1.f / lrow0;
    const float inv1 = 1.f / lrow1;
    const int b = bh >> 4, h = bh & 15;
    const int r0 = m0 + wid * 16 + (lane >> 2);
    #pragma unroll
    for (int nt = 0; nt < 16; nt++) {
        const int gc = h * HD + nt * 8 + (lane & 3) * 2;
        split_store2(Ohi, Olo, (size_t)(b * S_LEN + r0) * DIM + gc,
                     of[nt][0] * inv0, of[nt][1] * inv0);
        split_store2(Ohi, Olo, (size_t)(b * S_LEN + r0 + 8) * DIM + gc,
                     of[nt][2] * inv1, of[nt][3] * inv1);
    }
}

// ---------------- launch ----------------
extern "C" void kernel_launch(void* const* d_in, const int* in_sizes, int n_in,
                              void* d_out, int out_size)
{
    const float* x          = (const float*)d_in[0];
    const float* k_cache    = (const float*)d_in[1];
    const float* v_cache    = (const float*)d_in[2];
    const float* attn_norm_w= (const float*)d_in[3];
    const float* ffn_norm_w = (const float*)d_in[4];
    const float* wq = (const float*)d_in[5];
    const float* bq = (const float*)d_in[6];
    const float* wk = (const float*)d_in[7];
    const float* bk = (const float*)d_in[8];
    const float* wv = (const float*)d_in[9];
    const float* bv = (const float*)d_in[10];
    const float* wo = (const float*)d_in[11];
    const float* bo = (const float*)d_in[12];
    const float* w_gate = (const float*)d_in[13];
    const float* b_gate = (const float*)d_in[14];
    const float* w_val  = (const float*)d_in[15];
    const float* b_val  = (const float*)d_in[16];
    const float* w_proj = (const float*)d_in[17];
    const float* b_proj = (const float*)d_in[18];
    const float* fcos   = (const float*)d_in[19];
    const float* fsin   = (const float*)d_in[20];

    float* out_x = (float*)d_out;
    float* out_k = out_x + OUT_X_ELEMS;
    float* out_v = out_k + OUT_KV_ELEMS;

    float *p_qt, *p_kt, *p_vt, *p_x1, *p_g;
    __nv_bfloat16 *p_hA_hi, *p_hA_lo, *p_h2_hi, *p_h2_lo, *p_o_hi, *p_o_lo, *p_gt_hi, *p_gt_lo;
    __nv_bfloat16 *p_q16h, *p_q16l, *p_k16h, *p_k16l, *p_v16;
    __nv_bfloat16 *p_wq_hi, *p_wq_lo, *p_wk_hi, *p_wk_lo, *p_wv_hi, *p_wv_lo, *p_wo_hi, *p_wo_lo;
    __nv_bfloat16 *p_wg_hi, *p_wg_lo, *p_wv2_hi, *p_wv2_lo, *p_wp_hi, *p_wp_lo;

    cudaGetSymbolAddress((void**)&p_qt, g_qt);
    cudaGetSymbolAddress((void**)&p_kt, g_kt);
    cudaGetSymbolAddress((void**)&p_vt, g_vt);
    cudaGetSymbolAddress((void**)&p_x1, g_x1);
    cudaGetSymbolAddress((void**)&p_g,  g_g);
    cudaGetSymbolAddress((void**)&p_hA_hi, g_hA_hi);
    cudaGetSymbolAddress((void**)&p_hA_lo, g_hA_lo);
    cudaGetSymbolAddress((void**)&p_h2_hi, g_h2_hi);
    cudaGetSymbolAddress((void**)&p_h2_lo, g_h2_lo);
    cudaGetSymbolAddress((void**)&p_o_hi,  g_o_hi);
    cudaGetSymbolAddress((void**)&p_o_lo,  g_o_lo);
    cudaGetSymbolAddress((void**)&p_gt_hi, g_gt_hi);
    cudaGetSymbolAddress((void**)&p_gt_lo, g_gt_lo);
    cudaGetSymbolAddress((void**)&p_q16h, g_q16h);
    cudaGetSymbolAddress((void**)&p_q16l, g_q16l);
    cudaGetSymbolAddress((void**)&p_k16h, g_k16h);
    cudaGetSymbolAddress((void**)&p_k16l, g_k16l);
    cudaGetSymbolAddress((void**)&p_v16,  g_v16);
    cudaGetSymbolAddress((void**)&p_wq_hi, g_wq_hi);
    cudaGetSymbolAddress((void**)&p_wq_lo, g_wq_lo);
    cudaGetSymbolAddress((void**)&p_wk_hi, g_wk_hi);
    cudaGetSymbolAddress((void**)&p_wk_lo, g_wk_lo);
    cudaGetSymbolAddress((void**)&p_wv_hi, g_wv_hi);
    cudaGetSymbolAddress((void**)&p_wv_lo, g_wv_lo);
    cudaGetSymbolAddress((void**)&p_wo_hi, g_wo_hi);
    cudaGetSymbolAddress((void**)&p_wo_lo, g_wo_lo);
    cudaGetSymbolAddress((void**)&p_wg_hi, g_wg_hi);
    cudaGetSymbolAddress((void**)&p_wg_lo, g_wg_lo);
    cudaGetSymbolAddress((void**)&p_wv2_hi, g_wv2_hi);
    cudaGetSymbolAddress((void**)&p_wv2_lo, g_wv2_lo);
    cudaGetSymbolAddress((void**)&p_wp_hi, g_wp_hi);
    cudaGetSymbolAddress((void**)&p_wp_lo, g_wp_lo);

    cudaFuncSetAttribute(gemm_mma<0>, cudaFuncAttributeMaxDynamicSharedMemorySize, GM_SMEM);
    cudaFuncSetAttribute(gemm_mma<1>, cudaFuncAttributeMaxDynamicSharedMemorySize, GM_SMEM);
    cudaFuncSetAttribute(gemm_mma<2>, cudaFuncAttributeMaxDynamicSharedMemorySize, GM_SMEM);
    cudaFuncSetAttribute(flash_mma, cudaFuncAttributeMaxDynamicSharedMemorySize, F_SMEM);

    // ---- weight conversion + transpose ----
    weight_conv_t<<<dim3(64, 64), 256>>>(wq, p_wq_hi, p_wq_lo, DIM, DIM);
    weight_conv_t<<<dim3(64, 64), 256>>>(wk, p_wk_hi, p_wk_lo, DIM, DIM);
    weight_conv_t<<<dim3(64, 64), 256>>>(wv, p_wv_hi, p_wv_lo, DIM, DIM);
    weight_conv_t<<<dim3(64, 64), 256>>>(wo, p_wo_hi, p_wo_lo, DIM, DIM);
    weight_conv_t<<<dim3(64, 256), 256>>>(w_gate, p_wg_hi,  p_wg_lo,  FF_DIM, DIM);
    weight_conv_t<<<dim3(64, 256), 256>>>(w_val,  p_wv2_hi, p_wv2_lo, FF_DIM, DIM);
    weight_conv_t<<<dim3(256, 64), 256>>>(w_proj, p_wp_hi,  p_wp_lo,  DIM, FF_DIM);

    // ---- attention block ----
    rmsnorm_split<<<ROWS, 256>>>(x, attn_norm_w, p_hA_hi, p_hA_lo);
    gemm_mma<0><<<dim3(8, 32), 256, GM_SMEM>>>(
        p_hA_hi, p_hA_lo, p_wq_hi, p_wq_lo, bq, nullptr, p_qt, nullptr, nullptr, ROWS, DIM, DIM);
    gemm_mma<0><<<dim3(8, 32), 256, GM_SMEM>>>(
        p_hA_hi, p_hA_lo, p_wk_hi, p_wk_lo, bk, nullptr, p_kt, nullptr, nullptr, ROWS, DIM, DIM);
    gemm_mma<0><<<dim3(8, 32), 256, GM_SMEM>>>(
        p_hA_hi, p_hA_lo, p_wv_hi, p_wv_lo, bv, nullptr, p_vt, nullptr, nullptr, ROWS, DIM, DIM);

    rope_q_kernel<<<16384, 256>>>(p_qt, fcos, fsin, p_q16h, p_q16l);
    rope_k_kernel<<<16384, 256>>>(p_kt, fcos, fsin, out_k, p_k16h, p_k16l);
    copy_v_kernel<<<8192, 256>>>(p_vt, out_v, p_v16);
    copy_cache_k<<<4096, 256>>>(k_cache, out_k, p_k16h, p_k16l);
    copy_cache_v<<<4096, 256>>>(v_cache, out_v, p_v16);

    flash_mma<<<dim3(S_LEN / FBM, BATCH * HEADS), 256, F_SMEM>>>(
        p_q16h, p_q16l, p_k16h, p_k16l, p_v16, p_o_hi, p_o_lo);

    gemm_mma<1><<<dim3(8, 32), 256, GM_SMEM>>>(
        p_o_hi, p_o_lo, p_wo_hi, p_wo_lo, bo, x, p_x1, nullptr, nullptr, ROWS, DIM, DIM);

    // ---- ffn block ----
    rmsnorm_split<<<ROWS, 256>>>(p_x1, ffn_norm_w, p_h2_hi, p_h2_lo);
    gemm_mma<0><<<dim3(32, 32), 256, GM_SMEM>>>(
        p_h2_hi, p_h2_lo, p_wg_hi, p_wg_lo, b_gate, nullptr, p_g, nullptr, nullptr, ROWS, FF_DIM, DIM);
    gemm_mma<2><<<dim3(32, 32), 256, GM_SMEM>>>(
        p_h2_hi, p_h2_lo, p_wv2_hi, p_wv2_lo, b_val, p_g, nullptr, p_gt_hi, p_gt_lo, ROWS, FF_DIM, DIM);
    gemm_mma<1><<<dim3(8, 32), 256, GM_SMEM>>>(
        p_gt_hi, p_gt_lo, p_wp_hi, p_wp_lo, b_proj, p_x1, out_x, nullptr, nullptr, ROWS, DIM, FF_DIM);
}